// round 1
// baseline (speedup 1.0000x reference)
#include <cuda_runtime.h>

// Problem constants
#define NB   16
#define TT   4096
#define DD   64
#define KK   1024
#define SS   8
#define NV   (NB*TT)          // 65536 vectors
#define TM   128              // rows per CTA
#define TKC  128              // codes per smem chunk
#define ZQ_ELEMS (NB*DD*TT)   // 4194304

// Scratch (device globals: allocation-free)
__device__ float        g_res[NV*DD];     // residual [n][d]
__device__ float        g_q[NV*DD];       // quantized accumulator [n][d]
__device__ float        g_hn[SS*KK];      // 0.5*||c||^2
__device__ float        g_loss[SS];
__device__ unsigned int g_cnt[SS*KK];

// ---- packed f32x2 helpers (sm_100+) ----
__device__ __forceinline__ unsigned long long pk2(float lo, float hi) {
    unsigned long long r;
    asm("mov.b64 %0, {%1,%2};" : "=l"(r) : "f"(lo), "f"(hi));
    return r;
}
__device__ __forceinline__ void upk2(unsigned long long v, float &lo, float &hi) {
    asm("mov.b64 {%0,%1}, %2;" : "=f"(lo), "=f"(hi) : "l"(v));
}
__device__ __forceinline__ void fma2(unsigned long long &c, unsigned long long a, unsigned long long b) {
    asm("fma.rn.f32x2 %0, %1, %2, %0;" : "+l"(c) : "l"(a), "l"(b));
}

// ---- transpose z [B,D,T] -> residual [(b,t),d]; also zero g_q ----
__global__ void transpose_in(const float* __restrict__ z) {
    __shared__ float tile[32][33];
    const int b  = blockIdx.z;
    const int t0 = blockIdx.x * 32;
    const int d0 = blockIdx.y * 32;
    #pragma unroll
    for (int j = 0; j < 32; j += 8) {
        int d = d0 + threadIdx.y + j;
        int t = t0 + threadIdx.x;
        tile[threadIdx.y + j][threadIdx.x] = z[(b*DD + d)*TT + t];
    }
    __syncthreads();
    #pragma unroll
    for (int j = 0; j < 32; j += 8) {
        int t = t0 + threadIdx.y + j;
        int d = d0 + threadIdx.x;
        int idx = (b*TT + t)*DD + d;
        g_res[idx] = tile[threadIdx.x][threadIdx.y + j];
        g_q[idx]   = 0.0f;
    }
}

// ---- transpose g_q [(b,t),d] -> out [B,D,T] ----
__global__ void transpose_out(float* __restrict__ out) {
    __shared__ float tile[32][33];
    const int b  = blockIdx.z;
    const int t0 = blockIdx.x * 32;
    const int d0 = blockIdx.y * 32;
    #pragma unroll
    for (int j = 0; j < 32; j += 8) {
        int t = t0 + threadIdx.y + j;
        int d = d0 + threadIdx.x;
        tile[threadIdx.y + j][threadIdx.x] = g_q[(b*TT + t)*DD + d];
    }
    __syncthreads();
    #pragma unroll
    for (int j = 0; j < 32; j += 8) {
        int d = d0 + threadIdx.y + j;
        int t = t0 + threadIdx.x;
        out[(b*DD + d)*TT + t] = tile[threadIdx.x][threadIdx.y + j];
    }
}

// ---- 0.5*||c||^2 for all 8192 codes ----
__global__ void halfnorms(const float* __restrict__ cbs) {
    int c = blockIdx.x * 128 + threadIdx.x;
    const float4* p = (const float4*)(cbs + c*DD);
    float s = 0.0f;
    #pragma unroll
    for (int i = 0; i < 16; i++) {
        float4 v = p[i];
        s += v.x*v.x + v.y*v.y + v.z*v.z + v.w*v.w;
    }
    g_hn[c] = 0.5f * s;
}

__global__ void zero_acc() {
    int i = blockIdx.x * 256 + threadIdx.x;
    if (i < SS*KK) g_cnt[i] = 0u;
    if (i < SS)    g_loss[i] = 0.0f;
}

// ---- main stage kernel: argmax(r.c - 0.5||c||^2) + residual/quant update ----
extern __shared__ float smem_dyn[];

__global__ __launch_bounds__(256, 2)
void rvq_stage(const float* __restrict__ cb, int stage) {
    float* As = smem_dyn;             // [64][128] d-major
    float* Bs = smem_dyn + DD*TM;     // [64][128] d-major

    const int tid  = threadIdx.x;
    const int tx   = tid & 15;
    const int ty   = tid >> 4;
    const int row0 = blockIdx.x * TM;

    // Load residual tile, transposed into smem (conflict-free stores)
    {
        const float4* src = (const float4*)(g_res + row0*DD);
        #pragma unroll
        for (int i = 0; i < 8; i++) {
            int idx = i*256 + tid;        // 0..2047 float4s
            int r  = idx & 127;
            int d4 = idx >> 7;
            float4 v = src[r*16 + d4];
            As[(d4*4+0)*TM + r] = v.x;
            As[(d4*4+1)*TM + r] = v.y;
            As[(d4*4+2)*TM + r] = v.z;
            As[(d4*4+3)*TM + r] = v.w;
        }
    }

    float bestv[8];
    int   besti[8];
    #pragma unroll
    for (int i = 0; i < 8; i++) { bestv[i] = -3.4e38f; besti[i] = 0; }

    for (int kc = 0; kc < KK; kc += TKC) {
        __syncthreads();
        {
            const float4* bsrc = (const float4*)(cb + kc*DD);
            #pragma unroll
            for (int i = 0; i < 8; i++) {
                int idx = i*256 + tid;
                int r  = idx & 127;
                int d4 = idx >> 7;
                float4 v = bsrc[r*16 + d4];
                Bs[(d4*4+0)*TKC + r] = v.x;
                Bs[(d4*4+1)*TKC + r] = v.y;
                Bs[(d4*4+2)*TKC + r] = v.z;
                Bs[(d4*4+3)*TKC + r] = v.w;
            }
        }
        __syncthreads();

        unsigned long long acc[8][4];
        #pragma unroll
        for (int i = 0; i < 8; i++)
            #pragma unroll
            for (int j = 0; j < 4; j++) acc[i][j] = 0ull;

        #pragma unroll 16
        for (int d = 0; d < DD; d++) {
            float4 a0 = *(const float4*)&As[d*TM + ty*8];
            float4 a1 = *(const float4*)&As[d*TM + ty*8 + 4];
            float4 b0 = *(const float4*)&Bs[d*TKC + tx*8];
            float4 b1 = *(const float4*)&Bs[d*TKC + tx*8 + 4];
            unsigned long long bp[4];
            bp[0] = pk2(b0.x, b0.y); bp[1] = pk2(b0.z, b0.w);
            bp[2] = pk2(b1.x, b1.y); bp[3] = pk2(b1.z, b1.w);
            float av[8] = {a0.x,a0.y,a0.z,a0.w,a1.x,a1.y,a1.z,a1.w};
            #pragma unroll
            for (int i = 0; i < 8; i++) {
                unsigned long long ad = pk2(av[i], av[i]);
                #pragma unroll
                for (int j = 0; j < 4; j++) fma2(acc[i][j], ad, bp[j]);
            }
        }

        // compare against running best (first-index wins on ties via strict >)
        float h[8];
        {
            const float* hrow = g_hn + stage*KK + kc + tx*8;
            #pragma unroll
            for (int j = 0; j < 8; j++) h[j] = hrow[j];
        }
        #pragma unroll
        for (int i = 0; i < 8; i++) {
            #pragma unroll
            for (int j = 0; j < 4; j++) {
                float lo, hi;
                upk2(acc[i][j], lo, hi);
                float s0 = lo - h[2*j];
                float s1 = hi - h[2*j+1];
                int c0 = kc + tx*8 + 2*j;
                if (s0 > bestv[i]) { bestv[i] = s0; besti[i] = c0; }
                if (s1 > bestv[i]) { bestv[i] = s1; besti[i] = c0 + 1; }
            }
        }
    }

    // cross-thread argmax reduce (16 threads per row), reuse Bs region
    float* redV = Bs;                       // [128][16]
    int*   redI = (int*)(Bs + TM*16);       // [128][16]
    int*   fin  = (int*)(Bs + TM*32);       // [128]
    __syncthreads();
    #pragma unroll
    for (int i = 0; i < 8; i++) {
        int row = ty*8 + i;
        redV[row*16 + tx] = bestv[i];
        redI[row*16 + tx] = besti[i];
    }
    __syncthreads();
    if (tid < TM) {
        float bv = redV[tid*16];
        int   bi = redI[tid*16];
        #pragma unroll
        for (int t = 1; t < 16; t++) {
            float v = redV[tid*16 + t];
            int   ii = redI[tid*16 + t];
            if (v > bv || (v == bv && ii < bi)) { bv = v; bi = ii; }
        }
        fin[tid] = bi;
        atomicAdd(&g_cnt[stage*KK + bi], 1u);
    }
    __syncthreads();

    // update phase: 2 threads per row, 32 d's each
    const int row  = tid >> 1;
    const int half = tid & 1;
    const int code = fin[row];
    const float4* qv   = (const float4*)(cb  + code*DD          + half*32);
    float4*       rout = (float4*)(g_res + (row0+row)*DD + half*32);
    float4*       qout = (float4*)(g_q   + (row0+row)*DD + half*32);
    float lsum = 0.0f;
    #pragma unroll
    for (int u = 0; u < 8; u++) {
        float4 q4 = qv[u];
        int dbase = half*32 + u*4;
        float r0 = As[(dbase+0)*TM + row];
        float r1 = As[(dbase+1)*TM + row];
        float r2 = As[(dbase+2)*TM + row];
        float r3 = As[(dbase+3)*TM + row];
        float e0 = q4.x - r0, e1 = q4.y - r1, e2 = q4.z - r2, e3 = q4.w - r3;
        lsum += e0*e0 + e1*e1 + e2*e2 + e3*e3;
        float4 rn; rn.x = r0 - q4.x; rn.y = r1 - q4.y; rn.z = r2 - q4.z; rn.w = r3 - q4.w;
        rout[u] = rn;
        float4 qa = qout[u];
        qa.x += q4.x; qa.y += q4.y; qa.z += q4.z; qa.w += q4.w;
        qout[u] = qa;
    }

    // block-reduce commitment-loss partial
    __syncthreads();
    #pragma unroll
    for (int o = 16; o > 0; o >>= 1) lsum += __shfl_down_sync(0xffffffffu, lsum, o);
    if ((tid & 31) == 0) redV[tid >> 5] = lsum;
    __syncthreads();
    if (tid == 0) {
        float tot = 0.0f;
        #pragma unroll
        for (int w = 0; w < 8; w++) tot += redV[w];
        atomicAdd(&g_loss[stage], tot);
    }
}

// ---- losses + perplexities -> tail of output ----
__global__ void finalize(float* __restrict__ out) {
    const int s = blockIdx.x;
    __shared__ float sh[256];
    float e = 0.0f;
    for (int k = threadIdx.x; k < KK; k += 256) {
        float p = (float)g_cnt[s*KK + k] / (float)NV;
        e += p * logf(p + 1e-10f);
    }
    sh[threadIdx.x] = e;
    __syncthreads();
    for (int o = 128; o > 0; o >>= 1) {
        if (threadIdx.x < o) sh[threadIdx.x] += sh[threadIdx.x + o];
        __syncthreads();
    }
    if (threadIdx.x == 0) {
        out[ZQ_ELEMS + s]      = g_loss[s] / (float)(NV*DD);
        out[ZQ_ELEMS + SS + s] = expf(-sh[0]);
    }
}

extern "C" void kernel_launch(void* const* d_in, const int* in_sizes, int n_in,
                              void* d_out, int out_size) {
    const float* z   = (const float*)d_in[0];
    const float* cbs = (const float*)d_in[1];
    float* out = (float*)d_out;

    cudaFuncSetAttribute(rvq_stage, cudaFuncAttributeMaxDynamicSharedMemorySize, 65536);

    dim3 tb(32, 8);
    transpose_in<<<dim3(TT/32, DD/32, NB), tb>>>(z);
    zero_acc<<<32, 256>>>();
    halfnorms<<<(SS*KK)/128, 128>>>(cbs);
    for (int s = 0; s < SS; s++) {
        rvq_stage<<<NV/TM, 256, 65536>>>(cbs + (size_t)s*KK*DD, s);
    }
    finalize<<<SS, 256>>>(out);
    transpose_out<<<dim3(TT/32, DD/32, NB), tb>>>(out);
}

// round 2
// speedup vs baseline: 1.0154x; 1.0154x over previous
#include <cuda_runtime.h>
#include <float.h>

// Problem constants
#define NB   16
#define TT   4096
#define DD   64
#define KK   1024
#define SS   8
#define NV   (NB*TT)          // 65536 vectors
#define TM   128              // rows per CTA
#define TKC  128              // codes per chunk
#define ZQ_ELEMS (NB*DD*TT)   // 4194304
#define ASTRIDE 66            // padded row stride (floats), 8B aligned, conflict-free
#define BBUF  (TM*ASTRIDE)    // floats per B buffer = 8448

// Scratch (device globals: allocation-free)
__device__ float        g_res[NV*DD];     // residual [n][d] row-major
__device__ float        g_q[NV*DD];       // quantized accumulator [n][d]
__device__ float        g_hn[SS*KK];      // 0.5*||c||^2
__device__ float        g_loss[SS];
__device__ unsigned int g_cnt[SS*KK];

typedef unsigned long long u64;

// ---- packed f32x2 helpers ----
__device__ __forceinline__ void upk2(u64 v, float &lo, float &hi) {
    asm("mov.b64 {%0,%1}, %2;" : "=f"(lo), "=f"(hi) : "l"(v));
}
__device__ __forceinline__ void fma2(u64 &c, u64 a, u64 b) {
    asm("fma.rn.f32x2 %0, %1, %2, %0;" : "+l"(c) : "l"(a), "l"(b));
}

// ---- cp.async helpers ----
__device__ __forceinline__ void cpa8(float* dst, const float* src) {
    unsigned int d = (unsigned int)__cvta_generic_to_shared(dst);
    asm volatile("cp.async.ca.shared.global [%0], [%1], 8;" :: "r"(d), "l"(src) : "memory");
}
__device__ __forceinline__ void cpa_commit() {
    asm volatile("cp.async.commit_group;" ::: "memory");
}
template<int N>
__device__ __forceinline__ void cpa_wait() {
    asm volatile("cp.async.wait_group %0;" :: "n"(N) : "memory");
}

// ---- transpose z [B,D,T] -> residual [(b,t),d]; also zero g_q ----
__global__ void transpose_in(const float* __restrict__ z) {
    __shared__ float tile[32][33];
    const int b  = blockIdx.z;
    const int t0 = blockIdx.x * 32;
    const int d0 = blockIdx.y * 32;
    #pragma unroll
    for (int j = 0; j < 32; j += 8) {
        int d = d0 + threadIdx.y + j;
        int t = t0 + threadIdx.x;
        tile[threadIdx.y + j][threadIdx.x] = z[(b*DD + d)*TT + t];
    }
    __syncthreads();
    #pragma unroll
    for (int j = 0; j < 32; j += 8) {
        int t = t0 + threadIdx.y + j;
        int d = d0 + threadIdx.x;
        int idx = (b*TT + t)*DD + d;
        g_res[idx] = tile[threadIdx.x][threadIdx.y + j];
        g_q[idx]   = 0.0f;
    }
}

// ---- transpose g_q [(b,t),d] -> out [B,D,T] ----
__global__ void transpose_out(float* __restrict__ out) {
    __shared__ float tile[32][33];
    const int b  = blockIdx.z;
    const int t0 = blockIdx.x * 32;
    const int d0 = blockIdx.y * 32;
    #pragma unroll
    for (int j = 0; j < 32; j += 8) {
        int t = t0 + threadIdx.y + j;
        int d = d0 + threadIdx.x;
        tile[threadIdx.y + j][threadIdx.x] = g_q[(b*TT + t)*DD + d];
    }
    __syncthreads();
    #pragma unroll
    for (int j = 0; j < 32; j += 8) {
        int d = d0 + threadIdx.y + j;
        int t = t0 + threadIdx.x;
        out[(b*DD + d)*TT + t] = tile[threadIdx.x][threadIdx.y + j];
    }
}

// ---- 0.5*||c||^2 for all 8192 codes ----
__global__ void halfnorms(const float* __restrict__ cbs) {
    int c = blockIdx.x * 128 + threadIdx.x;
    const float4* p = (const float4*)(cbs + c*DD);
    float s = 0.0f;
    #pragma unroll
    for (int i = 0; i < 16; i++) {
        float4 v = p[i];
        s += v.x*v.x + v.y*v.y + v.z*v.z + v.w*v.w;
    }
    g_hn[c] = 0.5f * s;
}

__global__ void zero_acc() {
    int i = blockIdx.x * 256 + threadIdx.x;
    if (i < SS*KK) g_cnt[i] = 0u;
    if (i < SS)    g_loss[i] = 0.0f;
}

// ---- main stage kernel ----
extern __shared__ float smem_dyn[];

__global__ __launch_bounds__(256, 1)
void rvq_stage(const float* __restrict__ cb, int stage) {
    float* As = smem_dyn;               // [128][66] rows row-major
    float* Bs = smem_dyn + TM*ASTRIDE;  // [2][128][66]

    const int tid  = threadIdx.x;
    const int tx   = tid & 15;          // 16 code-lanes: codes j*16+tx
    const int ty   = tid >> 4;          // 16 row-groups: rows ty*8+i
    const int row0 = blockIdx.x * TM;

    // --- prologue: async-load A tile + B chunks 0,1 ---
    {
        const float* asrc = g_res + (size_t)row0*DD;
        #pragma unroll
        for (int i = 0; i < 16; i++) {
            int op = i*256 + tid;       // 0..4095, 8B granules
            int r  = op >> 5;
            int c  = op & 31;
            cpa8(As + r*ASTRIDE + c*2, asrc + r*DD + c*2);
        }
        #pragma unroll
        for (int i = 0; i < 16; i++) {
            int op = i*256 + tid;
            int r  = op >> 5;
            int c  = op & 31;
            cpa8(Bs + r*ASTRIDE + c*2, cb + r*DD + c*2);
        }
        cpa_commit();                   // group: {A, B0}
        #pragma unroll
        for (int i = 0; i < 16; i++) {
            int op = i*256 + tid;
            int r  = op >> 5;
            int c  = op & 31;
            cpa8(Bs + BBUF + r*ASTRIDE + c*2, cb + (TKC + r)*DD + c*2);
        }
        cpa_commit();                   // group: {B1}
    }

    float bestv[8];
    int   besti[8];
    #pragma unroll
    for (int i = 0; i < 8; i++) { bestv[i] = -FLT_MAX; besti[i] = 0; }

    u64 acc[8][8];
    #pragma unroll
    for (int i = 0; i < 8; i++)
        #pragma unroll
        for (int j = 0; j < 8; j++) acc[i][j] = 0ull;

    const float* Arow = As + ty*8*ASTRIDE;

    for (int ch = 0; ch < 8; ch++) {
        if (ch < 7) cpa_wait<1>(); else cpa_wait<0>();
        __syncthreads();

        const float* B = Bs + (ch & 1)*BBUF + tx*ASTRIDE;

        #pragma unroll 2
        for (int d2 = 0; d2 < 32; d2++) {
            u64 a[8], b[8];
            #pragma unroll
            for (int i = 0; i < 8; i++)
                a[i] = *(const u64*)(Arow + i*ASTRIDE + 2*d2);
            #pragma unroll
            for (int j = 0; j < 8; j++)
                b[j] = *(const u64*)(B + j*16*ASTRIDE + 2*d2);
            #pragma unroll
            for (int i = 0; i < 8; i++)
                #pragma unroll
                for (int j = 0; j < 8; j++)
                    fma2(acc[i][j], a[i], b[j]);
        }

        // fold partial sums, compare (first-index tie-break: strict >, ascending idx)
        const int kc = ch * TKC;
        #pragma unroll
        for (int j = 0; j < 8; j++) {
            float h = __ldg(&g_hn[stage*KK + kc + j*16 + tx]);
            int idx = kc + j*16 + tx;
            #pragma unroll
            for (int i = 0; i < 8; i++) {
                float lo, hi;
                upk2(acc[i][j], lo, hi);
                float s = lo + hi - h;
                if (s > bestv[i]) { bestv[i] = s; besti[i] = idx; }
                acc[i][j] = 0ull;
            }
        }

        __syncthreads();   // everyone done reading this buffer
        if (ch < 6) {
            const float* bsrc = cb + (size_t)(ch + 2)*TKC*DD;
            float* bdst = Bs + (ch & 1)*BBUF;
            #pragma unroll
            for (int i = 0; i < 16; i++) {
                int op = i*256 + tid;
                int r  = op >> 5;
                int c  = op & 31;
                cpa8(bdst + r*ASTRIDE + c*2, bsrc + r*DD + c*2);
            }
            cpa_commit();
        }
    }

    // --- cross-thread argmax reduce (16 lanes per row), reuse Bs region ---
    float* redV = Bs;                         // [128][16]
    int*   redI = (int*)(Bs + TM*16);         // [128][16]
    int*   fin  = (int*)(Bs + TM*32);         // [128]
    #pragma unroll
    for (int i = 0; i < 8; i++) {
        int row = ty*8 + i;
        redV[row*16 + tx] = bestv[i];
        redI[row*16 + tx] = besti[i];
    }
    __syncthreads();
    if (tid < TM) {
        float bv = redV[tid*16];
        int   bi = redI[tid*16];
        #pragma unroll
        for (int t = 1; t < 16; t++) {
            float v = redV[tid*16 + t];
            int  ii = redI[tid*16 + t];
            if (v > bv || (v == bv && ii < bi)) { bv = v; bi = ii; }
        }
        fin[tid] = bi;
        atomicAdd(&g_cnt[stage*KK + bi], 1u);
    }
    __syncthreads();

    // --- update phase: 2 threads per row, 32 d's each ---
    const int row  = tid >> 1;
    const int half = tid & 1;
    const int code = fin[row];
    const float4* qv   = (const float4*)(cb + (size_t)code*DD + half*32);
    float4*       rout = (float4*)(g_res + (size_t)(row0+row)*DD + half*32);
    float4*       qout = (float4*)(g_q   + (size_t)(row0+row)*DD + half*32);
    const float*  arow = As + row*ASTRIDE + half*32;
    float lsum = 0.0f;
    #pragma unroll
    for (int u = 0; u < 8; u++) {
        float4 q4 = qv[u];
        float r0 = arow[u*4+0];
        float r1 = arow[u*4+1];
        float r2 = arow[u*4+2];
        float r3 = arow[u*4+3];
        float e0 = q4.x - r0, e1 = q4.y - r1, e2 = q4.z - r2, e3 = q4.w - r3;
        lsum += e0*e0 + e1*e1 + e2*e2 + e3*e3;
        float4 rn; rn.x = r0 - q4.x; rn.y = r1 - q4.y; rn.z = r2 - q4.z; rn.w = r3 - q4.w;
        rout[u] = rn;
        float4 qa = qout[u];
        qa.x += q4.x; qa.y += q4.y; qa.z += q4.z; qa.w += q4.w;
        qout[u] = qa;
    }

    // --- block-reduce commitment-loss partial ---
    __syncthreads();
    #pragma unroll
    for (int o = 16; o > 0; o >>= 1) lsum += __shfl_down_sync(0xffffffffu, lsum, o);
    if ((tid & 31) == 0) redV[tid >> 5] = lsum;
    __syncthreads();
    if (tid == 0) {
        float tot = 0.0f;
        #pragma unroll
        for (int w = 0; w < 8; w++) tot += redV[w];
        atomicAdd(&g_loss[stage], tot);
    }
}

// ---- losses + perplexities -> tail of output ----
__global__ void finalize(float* __restrict__ out) {
    const int s = blockIdx.x;
    __shared__ float sh[256];
    float e = 0.0f;
    for (int k = threadIdx.x; k < KK; k += 256) {
        float p = (float)g_cnt[s*KK + k] / (float)NV;
        e += p * logf(p + 1e-10f);
    }
    sh[threadIdx.x] = e;
    __syncthreads();
    for (int o = 128; o > 0; o >>= 1) {
        if (threadIdx.x < o) sh[threadIdx.x] += sh[threadIdx.x + o];
        __syncthreads();
    }
    if (threadIdx.x == 0) {
        out[ZQ_ELEMS + s]      = g_loss[s] / (float)(NV*DD);
        out[ZQ_ELEMS + SS + s] = expf(-sh[0]);
    }
}

extern "C" void kernel_launch(void* const* d_in, const int* in_sizes, int n_in,
                              void* d_out, int out_size) {
    const float* z   = (const float*)d_in[0];
    const float* cbs = (const float*)d_in[1];
    float* out = (float*)d_out;

    static int smem_set = 0;
    if (!smem_set) {
        cudaFuncSetAttribute(rvq_stage, cudaFuncAttributeMaxDynamicSharedMemorySize,
                             (TM*ASTRIDE + 2*BBUF) * 4);
        smem_set = 1;
    }

    dim3 tb(32, 8);
    transpose_in<<<dim3(TT/32, DD/32, NB), tb>>>(z);
    zero_acc<<<32, 256>>>();
    halfnorms<<<(SS*KK)/128, 128>>>(cbs);
    for (int s = 0; s < SS; s++) {
        rvq_stage<<<NV/TM, 256, (TM*ASTRIDE + 2*BBUF)*4>>>(cbs + (size_t)s*KK*DD, s);
    }
    finalize<<<SS, 256>>>(out);
    transpose_out<<<dim3(TT/32, DD/32, NB), tb>>>(out);
}

// round 5
// speedup vs baseline: 1.4608x; 1.4387x over previous
#include <cuda_runtime.h>
#include <cuda_fp16.h>
#include <float.h>
#include <cstdint>

#define NB   16
#define TT   4096
#define DD   64
#define KK   1024
#define SS   8
#define NV   (NB*TT)
#define TM   128
#define ZQ_ELEMS (NB*DD*TT)

// ---- device scratch ----
__device__ float        g_res[NV*DD];
__device__ float        g_q[NV*DD];
__device__ __half       g_resh16[NV*DD];
__device__ __half       g_resl16[NV*DD];
__device__ __half       g_cbh16[SS*KK*DD];
__device__ __half       g_cbl16[SS*KK*DD];
__device__ float        g_hn[SS*KK];
__device__ float        g_loss[SS];
__device__ unsigned int g_cnt[SS*KK];

// ---- smem layout (bytes) ----
#define RSTR     144            // padded row stride bytes (72 fp16)
#define TILE_B   (128*RSTR)     // 18432
#define SM_HN    0
#define SM_FIN   4096
#define SM_RED   4608
#define SM_AH    8192
#define SM_AL    (SM_AH + TILE_B)
#define SM_B0    45056
#define SM_B1    (SM_B0 + 2*TILE_B)
#define SM_TOTAL (SM_B1 + 2*TILE_B)   // 118784

// ---- PTX helpers ----
__device__ __forceinline__ void cpa16(uint32_t daddr, const void* src) {
    asm volatile("cp.async.cg.shared.global [%0], [%1], 16;" :: "r"(daddr), "l"(src) : "memory");
}
__device__ __forceinline__ void cpa_commit() { asm volatile("cp.async.commit_group;" ::: "memory"); }
__device__ __forceinline__ void cpa_wait0()  { asm volatile("cp.async.wait_group 0;" ::: "memory"); }
__device__ __forceinline__ void cpa_wait1()  { asm volatile("cp.async.wait_group 1;" ::: "memory"); }

__device__ __forceinline__ void ldsm_x4(uint32_t* r, uint32_t a) {
    asm volatile("ldmatrix.sync.aligned.m8n8.x4.shared.b16 {%0,%1,%2,%3}, [%4];"
        : "=r"(r[0]), "=r"(r[1]), "=r"(r[2]), "=r"(r[3]) : "r"(a));
}
__device__ __forceinline__ void mma16816(float* c, const uint32_t* a, const uint32_t* b) {
    asm volatile("mma.sync.aligned.m16n8k16.row.col.f32.f16.f16.f32 "
        "{%0,%1,%2,%3}, {%4,%5,%6,%7}, {%8,%9}, {%0,%1,%2,%3};"
        : "+f"(c[0]), "+f"(c[1]), "+f"(c[2]), "+f"(c[3])
        : "r"(a[0]), "r"(a[1]), "r"(a[2]), "r"(a[3]), "r"(b[0]), "r"(b[1]));
}

// ---- transpose z [B,D,T] -> g_res [(b,t),d] + fp16 hi/lo; zero g_q ----
__global__ void transpose_in(const float* __restrict__ z) {
    __shared__ float tile[32][33];
    const int b  = blockIdx.z;
    const int t0 = blockIdx.x * 32;
    const int d0 = blockIdx.y * 32;
    #pragma unroll
    for (int j = 0; j < 32; j += 8)
        tile[threadIdx.y + j][threadIdx.x] = z[(b*DD + d0 + threadIdx.y + j)*TT + t0 + threadIdx.x];
    __syncthreads();
    #pragma unroll
    for (int j = 0; j < 32; j += 8) {
        int t = t0 + threadIdx.y + j;
        int d = d0 + threadIdx.x;
        int n = b*TT + t;
        float v = tile[threadIdx.x][threadIdx.y + j];
        g_res[n*DD + d] = v;
        g_q[n*DD + d]   = 0.0f;
        __half h = __float2half_rn(v);
        __half l = __float2half_rn(v - __half2float(h));
        g_resh16[n*DD + d] = h;
        g_resl16[n*DD + d] = l;
    }
}

__global__ void transpose_out(float* __restrict__ out) {
    __shared__ float tile[32][33];
    const int b  = blockIdx.z;
    const int t0 = blockIdx.x * 32;
    const int d0 = blockIdx.y * 32;
    #pragma unroll
    for (int j = 0; j < 32; j += 8)
        tile[threadIdx.y + j][threadIdx.x] = g_q[((size_t)b*TT + t0 + threadIdx.y + j)*DD + d0 + threadIdx.x];
    __syncthreads();
    #pragma unroll
    for (int j = 0; j < 32; j += 8)
        out[((size_t)b*DD + d0 + threadIdx.y + j)*TT + t0 + threadIdx.x] = tile[threadIdx.x][threadIdx.y + j];
}

// ---- codebook split + halfnorms ----
__global__ void cb_split(const float* __restrict__ cbs) {
    int g = blockIdx.x * 128 + threadIdx.x;   // 0..8191
    const float* src = cbs + (size_t)g * DD;
    float s2 = 0.0f;
    #pragma unroll
    for (int k = 0; k < DD; k++) {
        float v = src[k];
        s2 += v*v;
        __half h = __float2half_rn(v);
        __half l = __float2half_rn(v - __half2float(h));
        g_cbh16[(size_t)g*DD + k] = h;
        g_cbl16[(size_t)g*DD + k] = l;
    }
    g_hn[g] = 0.5f * s2;
}

__global__ void zero_acc() {
    int i = blockIdx.x * 256 + threadIdx.x;
    if (i < SS*KK) g_cnt[i] = 0u;
    if (i < SS)    g_loss[i] = 0.0f;
}

// ---- main stage kernel ----
extern __shared__ char smem_raw[];

__global__ __launch_bounds__(256, 1)
void rvq_stage(const float* __restrict__ cb, int stage) {
    const int tid  = threadIdx.x;
    const int w    = tid >> 5;
    const int lane = tid & 31;
    const int row0 = blockIdx.x * TM;
    uint32_t sb;
    asm("{ .reg .u64 t; cvta.to.shared.u64 t, %1; cvt.u32.u64 %0, t; }" : "=r"(sb) : "l"(smem_raw));

    float* hn_s = (float*)(smem_raw + SM_HN);
    int*   fin  = (int*)(smem_raw + SM_FIN);
    float* red  = (float*)(smem_raw + SM_RED);

    // ---- prologue: cp.async A(h,l) + hn + B0 (group0), B1 (group1) ----
    {
        const char* ah = (const char*)(g_resh16 + (size_t)row0*DD);
        const char* al = (const char*)(g_resl16 + (size_t)row0*DD);
        #pragma unroll
        for (int g = 0; g < 4; g++) {
            int idx = g*256 + tid;              // 1024 granules per tile
            int r = idx >> 3, cc = idx & 7;
            uint32_t dof = r*RSTR + cc*16;
            int sof = r*128 + cc*16;
            cpa16(sb + SM_AH + dof, ah + sof);
            cpa16(sb + SM_AL + dof, al + sof);
        }
        cpa16(sb + SM_HN + tid*16, (const char*)(g_hn + stage*KK) + tid*16);
        const char* bh = (const char*)(g_cbh16 + (size_t)stage*KK*DD);
        const char* bl = (const char*)(g_cbl16 + (size_t)stage*KK*DD);
        #pragma unroll
        for (int g = 0; g < 4; g++) {
            int idx = g*256 + tid;
            int r = idx >> 3, cc = idx & 7;
            uint32_t dof = r*RSTR + cc*16;
            int sof = r*128 + cc*16;
            cpa16(sb + SM_B0 + dof,          bh + sof);
            cpa16(sb + SM_B0 + TILE_B + dof, bl + sof);
        }
        cpa_commit();   // group0: A + hn + B0
        #pragma unroll
        for (int g = 0; g < 4; g++) {
            int idx = g*256 + tid;
            int r = idx >> 3, cc = idx & 7;
            uint32_t dof = r*RSTR + cc*16;
            int sof = r*128 + cc*16;
            cpa16(sb + SM_B1 + dof,          bh + 16384 + sof);
            cpa16(sb + SM_B1 + TILE_B + dof, bl + 16384 + sof);
        }
        cpa_commit();   // group1: B1
    }

    uint32_t ahf[4][4], alf[4][4];
    const uint32_t a_addr = sb + SM_AH + (w*16 + (lane & 15))*RSTR + (lane >> 4)*16;
    // B fragment addresses (non-trans x4): matrices {codes0-7/k0-7, codes0-7/k8-15,
    // codes8-15/k0-7, codes8-15/k8-15} -> regs b0..b3
    const uint32_t b_lane = ((lane & 7) + ((lane >> 4) & 1)*8)*RSTR + ((lane >> 3) & 1)*16;

    float bv0 = -FLT_MAX, bv1 = -FLT_MAX;
    int   bi0 = 0,        bi1 = 0;

    for (int c = 0; c < 8; c++) {
        if (c < 7) cpa_wait1(); else cpa_wait0();
        __syncthreads();
        if (c == 0) {
            #pragma unroll
            for (int s = 0; s < 4; s++) {
                ldsm_x4(ahf[s], a_addr + s*32);
                ldsm_x4(alf[s], a_addr + TILE_B + s*32);
            }
        }
        const uint32_t bbase = sb + ((c & 1) ? SM_B1 : SM_B0) + b_lane;

        float acc[16][4];
        #pragma unroll
        for (int i = 0; i < 16; i++)
            #pragma unroll
            for (int j = 0; j < 4; j++) acc[i][j] = 0.0f;

        #pragma unroll
        for (int s = 0; s < 4; s++) {
            #pragma unroll
            for (int nb2 = 0; nb2 < 8; nb2++) {
                uint32_t ba = bbase + nb2*(16*RSTR) + s*32;
                uint32_t bh[4], bl[4];
                ldsm_x4(bh, ba);
                ldsm_x4(bl, ba + TILE_B);
                mma16816(acc[nb2*2],   ahf[s], bh);
                mma16816(acc[nb2*2],   ahf[s], bl);
                mma16816(acc[nb2*2],   alf[s], bh);
                mma16816(acc[nb2*2+1], ahf[s], bh + 2);
                mma16816(acc[nb2*2+1], ahf[s], bl + 2);
                mma16816(acc[nb2*2+1], alf[s], bh + 2);
            }
        }

        // argmax fold (thread owns rows w*16 + lane/4 and +8; cols (lane&3)*2 per n8 block)
        const int cb0 = c*128 + (lane & 3)*2;
        #pragma unroll
        for (int nb = 0; nb < 16; nb++) {
            int col = cb0 + nb*8;
            float h0 = hn_s[col], h1 = hn_s[col + 1];
            float s00 = acc[nb][0] - h0;
            float s01 = acc[nb][1] - h1;
            float s10 = acc[nb][2] - h0;
            float s11 = acc[nb][3] - h1;
            if (s00 > bv0) { bv0 = s00; bi0 = col; }
            if (s01 > bv0) { bv0 = s01; bi0 = col + 1; }
            if (s10 > bv1) { bv1 = s10; bi1 = col; }
            if (s11 > bv1) { bv1 = s11; bi1 = col + 1; }
        }

        __syncthreads();
        if (c < 6) {
            size_t co = (size_t)(c + 2) * 16384;
            const char* bh = (const char*)(g_cbh16 + (size_t)stage*KK*DD) + co;
            const char* bl = (const char*)(g_cbl16 + (size_t)stage*KK*DD) + co;
            uint32_t bdst = sb + ((c & 1) ? SM_B1 : SM_B0);
            #pragma unroll
            for (int g = 0; g < 4; g++) {
                int idx = g*256 + tid;
                int r = idx >> 3, cc2 = idx & 7;
                uint32_t dof = r*RSTR + cc2*16;
                int sof = r*128 + cc2*16;
                cpa16(bdst + dof,          bh + sof);
                cpa16(bdst + TILE_B + dof, bl + sof);
            }
            cpa_commit();
        }
    }

    // ---- cross-lane reduce over the 4 lanes sharing a row ----
    #pragma unroll
    for (int off = 1; off <= 2; off <<= 1) {
        float ov = __shfl_xor_sync(0xffffffffu, bv0, off);
        int   oi = __shfl_xor_sync(0xffffffffu, bi0, off);
        if (ov > bv0 || (ov == bv0 && oi < bi0)) { bv0 = ov; bi0 = oi; }
        ov = __shfl_xor_sync(0xffffffffu, bv1, off);
        oi = __shfl_xor_sync(0xffffffffu, bi1, off);
        if (ov > bv1 || (ov == bv1 && oi < bi1)) { bv1 = ov; bi1 = oi; }
    }
    if ((lane & 3) == 0) {
        int r0 = w*16 + (lane >> 2);
        fin[r0]     = bi0;
        fin[r0 + 8] = bi1;
        atomicAdd(&g_cnt[stage*KK + bi0], 1u);
        atomicAdd(&g_cnt[stage*KK + bi1], 1u);
    }
    __syncthreads();

    // ---- update: 2 threads per row ----
    const int row  = tid >> 1;
    const int half = tid & 1;
    const int code = fin[row];
    const float4* qv   = (const float4*)(cb + (size_t)code*DD + half*32);
    float4*       rptr = (float4*)(g_res + (size_t)(row0+row)*DD + half*32);
    float4*       qptr = (float4*)(g_q   + (size_t)(row0+row)*DD + half*32);
    __half* th = g_resh16 + (size_t)(row0+row)*DD + half*32;
    __half* tl = g_resl16 + (size_t)(row0+row)*DD + half*32;
    float lsum = 0.0f;
    #pragma unroll
    for (int u = 0; u < 8; u++) {
        float4 q4 = qv[u];
        float4 r4 = rptr[u];
        float e0 = q4.x - r4.x, e1 = q4.y - r4.y, e2 = q4.z - r4.z, e3 = q4.w - r4.w;
        lsum += e0*e0 + e1*e1 + e2*e2 + e3*e3;
        float4 rn; rn.x = -e0; rn.y = -e1; rn.z = -e2; rn.w = -e3;
        rptr[u] = rn;
        float4 qa = qptr[u];
        qa.x += q4.x; qa.y += q4.y; qa.z += q4.z; qa.w += q4.w;
        qptr[u] = qa;
        float nv[4] = {rn.x, rn.y, rn.z, rn.w};
        #pragma unroll
        for (int e = 0; e < 4; e++) {
            __half h = __float2half_rn(nv[e]);
            __half l = __float2half_rn(nv[e] - __half2float(h));
            th[u*4 + e] = h;
            tl[u*4 + e] = l;
        }
    }

    __syncthreads();
    #pragma unroll
    for (int o = 16; o > 0; o >>= 1) lsum += __shfl_down_sync(0xffffffffu, lsum, o);
    if ((tid & 31) == 0) red[tid >> 5] = lsum;
    __syncthreads();
    if (tid == 0) {
        float tot = 0.0f;
        #pragma unroll
        for (int ww = 0; ww < 8; ww++) tot += red[ww];
        atomicAdd(&g_loss[stage], tot);
    }
}

// ---- losses + perplexities ----
__global__ void finalize(float* __restrict__ out) {
    const int s = blockIdx.x;
    __shared__ float sh[256];
    float e = 0.0f;
    for (int k = threadIdx.x; k < KK; k += 256) {
        float p = (float)g_cnt[s*KK + k] / (float)NV;
        e += p * logf(p + 1e-10f);
    }
    sh[threadIdx.x] = e;
    __syncthreads();
    for (int o = 128; o > 0; o >>= 1) {
        if (threadIdx.x < o) sh[threadIdx.x] += sh[threadIdx.x + o];
        __syncthreads();
    }
    if (threadIdx.x == 0) {
        out[ZQ_ELEMS + s]      = g_loss[s] / (float)(NV*DD);
        out[ZQ_ELEMS + SS + s] = expf(-sh[0]);
    }
}

extern "C" void kernel_launch(void* const* d_in, const int* in_sizes, int n_in,
                              void* d_out, int out_size) {
    const float* z   = (const float*)d_in[0];
    const float* cbs = (const float*)d_in[1];
    float* out = (float*)d_out;

    static int inited = 0;
    if (!inited) {
        cudaFuncSetAttribute(rvq_stage, cudaFuncAttributeMaxDynamicSharedMemorySize, SM_TOTAL);
        inited = 1;
    }

    dim3 tb(32, 8);
    transpose_in<<<dim3(TT/32, DD/32, NB), tb>>>(z);
    zero_acc<<<32, 256>>>();
    cb_split<<<(SS*KK)/128, 128>>>(cbs);
    for (int s = 0; s < SS; s++) {
        rvq_stage<<<NV/TM, 256, SM_TOTAL>>>(cbs + (size_t)s*KK*DD, s);
    }
    finalize<<<SS, 256>>>(out);
    transpose_out<<<dim3(TT/32, DD/32, NB), tb>>>(out);
}

// round 6
// speedup vs baseline: 1.6067x; 1.0999x over previous
#include <cuda_runtime.h>
#include <cuda_fp16.h>
#include <float.h>
#include <cstdint>

#define NB   16
#define TT   4096
#define DD   64
#define KK   1024
#define SS   8
#define NV   (NB*TT)
#define TM   128
#define ZQ_ELEMS (NB*DD*TT)

// ---- device scratch ----
__device__ float        g_res[NV*DD];
__device__ float        g_q[NV*DD];
__device__ __half       g_resh16[NV*DD];
__device__ __half       g_resl16[NV*DD];
__device__ __half       g_cbh16[SS*KK*DD];
__device__ __half       g_cbl16[SS*KK*DD];
__device__ float        g_hn[SS*KK];
__device__ float        g_loss[SS];
__device__ unsigned int g_cnt[SS*KK];

// ---- smem layout (bytes) ----
#define RSTR     144            // padded row stride bytes (72 fp16)
#define TILE_B   (128*RSTR)     // 18432
#define SM_HN    0
#define SM_FIN   4096
#define SM_REDV  4608
#define SM_REDI  5632
#define SM_RED   6656
#define SM_AH    8192
#define SM_AL    (SM_AH + TILE_B)
#define SM_B0    45056
#define SM_B1    (SM_B0 + 2*TILE_B)
#define SM_TOTAL (SM_B1 + 2*TILE_B)   // 118784

// ---- PTX helpers ----
__device__ __forceinline__ void cpa16(uint32_t daddr, const void* src) {
    asm volatile("cp.async.cg.shared.global [%0], [%1], 16;" :: "r"(daddr), "l"(src) : "memory");
}
__device__ __forceinline__ void cpa_commit() { asm volatile("cp.async.commit_group;" ::: "memory"); }
__device__ __forceinline__ void cpa_wait0()  { asm volatile("cp.async.wait_group 0;" ::: "memory"); }
__device__ __forceinline__ void cpa_wait1()  { asm volatile("cp.async.wait_group 1;" ::: "memory"); }

__device__ __forceinline__ void ldsm_x4(uint32_t* r, uint32_t a) {
    asm volatile("ldmatrix.sync.aligned.m8n8.x4.shared.b16 {%0,%1,%2,%3}, [%4];"
        : "=r"(r[0]), "=r"(r[1]), "=r"(r[2]), "=r"(r[3]) : "r"(a));
}
__device__ __forceinline__ void mma16816(float* c, const uint32_t* a, const uint32_t* b) {
    asm volatile("mma.sync.aligned.m16n8k16.row.col.f32.f16.f16.f32 "
        "{%0,%1,%2,%3}, {%4,%5,%6,%7}, {%8,%9}, {%0,%1,%2,%3};"
        : "+f"(c[0]), "+f"(c[1]), "+f"(c[2]), "+f"(c[3])
        : "r"(a[0]), "r"(a[1]), "r"(a[2]), "r"(a[3]), "r"(b[0]), "r"(b[1]));
}

// ---- transpose z [B,D,T] -> g_res [(b,t),d] + fp16 hi/lo; zero g_q ----
__global__ void transpose_in(const float* __restrict__ z) {
    __shared__ float tile[32][33];
    const int b  = blockIdx.z;
    const int t0 = blockIdx.x * 32;
    const int d0 = blockIdx.y * 32;
    #pragma unroll
    for (int j = 0; j < 32; j += 8)
        tile[threadIdx.y + j][threadIdx.x] = z[(b*DD + d0 + threadIdx.y + j)*TT + t0 + threadIdx.x];
    __syncthreads();
    #pragma unroll
    for (int j = 0; j < 32; j += 8) {
        int t = t0 + threadIdx.y + j;
        int d = d0 + threadIdx.x;
        int n = b*TT + t;
        float v = tile[threadIdx.x][threadIdx.y + j];
        g_res[n*DD + d] = v;
        g_q[n*DD + d]   = 0.0f;
        __half h = __float2half_rn(v);
        __half l = __float2half_rn(v - __half2float(h));
        g_resh16[n*DD + d] = h;
        g_resl16[n*DD + d] = l;
    }
}

__global__ void transpose_out(float* __restrict__ out) {
    __shared__ float tile[32][33];
    const int b  = blockIdx.z;
    const int t0 = blockIdx.x * 32;
    const int d0 = blockIdx.y * 32;
    #pragma unroll
    for (int j = 0; j < 32; j += 8)
        tile[threadIdx.y + j][threadIdx.x] = g_q[((size_t)b*TT + t0 + threadIdx.y + j)*DD + d0 + threadIdx.x];
    __syncthreads();
    #pragma unroll
    for (int j = 0; j < 32; j += 8)
        out[((size_t)b*DD + d0 + threadIdx.y + j)*TT + t0 + threadIdx.x] = tile[threadIdx.x][threadIdx.y + j];
}

// ---- codebook split + halfnorms ----
__global__ void cb_split(const float* __restrict__ cbs) {
    int g = blockIdx.x * 128 + threadIdx.x;   // 0..8191
    const float* src = cbs + (size_t)g * DD;
    float s2 = 0.0f;
    #pragma unroll
    for (int k = 0; k < DD; k++) {
        float v = src[k];
        s2 += v*v;
        __half h = __float2half_rn(v);
        __half l = __float2half_rn(v - __half2float(h));
        g_cbh16[(size_t)g*DD + k] = h;
        g_cbl16[(size_t)g*DD + k] = l;
    }
    g_hn[g] = 0.5f * s2;
}

__global__ void zero_acc() {
    int i = blockIdx.x * 256 + threadIdx.x;
    if (i < SS*KK) g_cnt[i] = 0u;
    if (i < SS)    g_loss[i] = 0.0f;
}

// ---- main stage kernel: 512 threads, 16 warps = 8 row-groups x 2 code-halves ----
extern __shared__ char smem_raw[];

__global__ __launch_bounds__(512, 1)
void rvq_stage(const float* __restrict__ cb, int stage) {
    const int tid  = threadIdx.x;
    const int w    = tid >> 5;
    const int lane = tid & 31;
    const int wrow = w >> 1;          // 0..7: rows wrow*16..+15
    const int wcol = w & 1;           // 0..1: codes wcol*64..+63 within chunk
    const int row0 = blockIdx.x * TM;
    uint32_t sb;
    asm("{ .reg .u64 t; cvta.to.shared.u64 t, %1; cvt.u32.u64 %0, t; }" : "=r"(sb) : "l"(smem_raw));

    float* hn_s = (float*)(smem_raw + SM_HN);
    int*   fin  = (int*)(smem_raw + SM_FIN);
    float* redV = (float*)(smem_raw + SM_REDV);   // [128][2]
    int*   redI = (int*)(smem_raw + SM_REDI);     // [128][2]
    float* red  = (float*)(smem_raw + SM_RED);

    // ---- prologue: cp.async A(h,l) + hn + B0 (group0), B1 (group1) ----
    {
        const char* ah = (const char*)(g_resh16 + (size_t)row0*DD);
        const char* al = (const char*)(g_resl16 + (size_t)row0*DD);
        #pragma unroll
        for (int g = 0; g < 2; g++) {
            int idx = g*512 + tid;              // 1024 granules per tile
            int r = idx >> 3, cc = idx & 7;
            uint32_t dof = r*RSTR + cc*16;
            int sof = r*128 + cc*16;
            cpa16(sb + SM_AH + dof, ah + sof);
            cpa16(sb + SM_AL + dof, al + sof);
        }
        if (tid < 256) cpa16(sb + SM_HN + tid*16, (const char*)(g_hn + stage*KK) + tid*16);
        const char* bh = (const char*)(g_cbh16 + (size_t)stage*KK*DD);
        const char* bl = (const char*)(g_cbl16 + (size_t)stage*KK*DD);
        #pragma unroll
        for (int g = 0; g < 2; g++) {
            int idx = g*512 + tid;
            int r = idx >> 3, cc = idx & 7;
            uint32_t dof = r*RSTR + cc*16;
            int sof = r*128 + cc*16;
            cpa16(sb + SM_B0 + dof,          bh + sof);
            cpa16(sb + SM_B0 + TILE_B + dof, bl + sof);
        }
        cpa_commit();   // group0: A + hn + B0
        #pragma unroll
        for (int g = 0; g < 2; g++) {
            int idx = g*512 + tid;
            int r = idx >> 3, cc = idx & 7;
            uint32_t dof = r*RSTR + cc*16;
            int sof = r*128 + cc*16;
            cpa16(sb + SM_B1 + dof,          bh + 16384 + sof);
            cpa16(sb + SM_B1 + TILE_B + dof, bl + 16384 + sof);
        }
        cpa_commit();   // group1: B1
    }

    uint32_t ahf[4][4], alf[4][4];
    const uint32_t a_addr = sb + SM_AH + (wrow*16 + (lane & 15))*RSTR + (lane >> 4)*16;
    const uint32_t b_lane = (wcol*64 + (lane & 7) + ((lane >> 4) & 1)*8)*RSTR + ((lane >> 3) & 1)*16;

    float bv0 = -FLT_MAX, bv1 = -FLT_MAX;
    int   bi0 = 0,        bi1 = 0;

    for (int c = 0; c < 8; c++) {
        if (c < 7) cpa_wait1(); else cpa_wait0();
        __syncthreads();
        if (c == 0) {
            #pragma unroll
            for (int s = 0; s < 4; s++) {
                ldsm_x4(ahf[s], a_addr + s*32);
                ldsm_x4(alf[s], a_addr + TILE_B + s*32);
            }
        }
        const uint32_t bbase = sb + ((c & 1) ? SM_B1 : SM_B0) + b_lane;
        const int cbase = c*128 + wcol*64 + (lane & 3)*2;

        // init accumulators with -0.5||c||^2 (HMMA accumulates on top)
        float acc[8][4];
        #pragma unroll
        for (int nb = 0; nb < 8; nb++) {
            float h0 = -hn_s[cbase + nb*8];
            float h1 = -hn_s[cbase + nb*8 + 1];
            acc[nb][0] = h0; acc[nb][1] = h1; acc[nb][2] = h0; acc[nb][3] = h1;
        }

        #pragma unroll
        for (int s = 0; s < 4; s++) {
            #pragma unroll
            for (int nb2 = 0; nb2 < 4; nb2++) {
                uint32_t ba = bbase + nb2*(16*RSTR) + s*32;
                uint32_t bh[4], bl[4];
                ldsm_x4(bh, ba);
                ldsm_x4(bl, ba + TILE_B);
                mma16816(acc[nb2*2],   ahf[s], bh);
                mma16816(acc[nb2*2],   ahf[s], bl);
                mma16816(acc[nb2*2],   alf[s], bh);
                mma16816(acc[nb2*2+1], ahf[s], bh + 2);
                mma16816(acc[nb2*2+1], ahf[s], bl + 2);
                mma16816(acc[nb2*2+1], alf[s], bh + 2);
            }
        }

        // argmax fold: thread owns rows wrow*16 + lane/4 and +8
        #pragma unroll
        for (int nb = 0; nb < 8; nb++) {
            int col = cbase + nb*8;
            if (acc[nb][0] > bv0) { bv0 = acc[nb][0]; bi0 = col; }
            if (acc[nb][1] > bv0) { bv0 = acc[nb][1]; bi0 = col + 1; }
            if (acc[nb][2] > bv1) { bv1 = acc[nb][2]; bi1 = col; }
            if (acc[nb][3] > bv1) { bv1 = acc[nb][3]; bi1 = col + 1; }
        }

        __syncthreads();
        if (c < 6) {
            size_t co = (size_t)(c + 2) * 16384;
            const char* bh = (const char*)(g_cbh16 + (size_t)stage*KK*DD) + co;
            const char* bl = (const char*)(g_cbl16 + (size_t)stage*KK*DD) + co;
            uint32_t bdst = sb + ((c & 1) ? SM_B1 : SM_B0);
            #pragma unroll
            for (int g = 0; g < 2; g++) {
                int idx = g*512 + tid;
                int r = idx >> 3, cc2 = idx & 7;
                uint32_t dof = r*RSTR + cc2*16;
                int sof = r*128 + cc2*16;
                cpa16(bdst + dof,          bh + sof);
                cpa16(bdst + TILE_B + dof, bl + sof);
            }
            cpa_commit();
        }
    }

    // ---- reduce over 4 lanes sharing a row ----
    #pragma unroll
    for (int off = 1; off <= 2; off <<= 1) {
        float ov = __shfl_xor_sync(0xffffffffu, bv0, off);
        int   oi = __shfl_xor_sync(0xffffffffu, bi0, off);
        if (ov > bv0 || (ov == bv0 && oi < bi0)) { bv0 = ov; bi0 = oi; }
        ov = __shfl_xor_sync(0xffffffffu, bv1, off);
        oi = __shfl_xor_sync(0xffffffffu, bi1, off);
        if (ov > bv1 || (ov == bv1 && oi < bi1)) { bv1 = ov; bi1 = oi; }
    }
    if ((lane & 3) == 0) {
        int r0 = wrow*16 + (lane >> 2);
        redV[r0*2 + wcol]       = bv0;  redI[r0*2 + wcol]       = bi0;
        redV[(r0 + 8)*2 + wcol] = bv1;  redI[(r0 + 8)*2 + wcol] = bi1;
    }
    __syncthreads();
    if (tid < TM) {
        float v0 = redV[tid*2], v1 = redV[tid*2 + 1];
        int   i0 = redI[tid*2], i1 = redI[tid*2 + 1];
        int   bi = (v1 > v0 || (v1 == v0 && i1 < i0)) ? i1 : i0;
        fin[tid] = bi;
        atomicAdd(&g_cnt[stage*KK + bi], 1u);
    }
    __syncthreads();

    // ---- update: 4 threads per row, 16 d's each ----
    const int row = tid >> 2;
    const int qt  = tid & 3;
    const int code = fin[row];
    const float4* qv   = (const float4*)(cb + (size_t)code*DD + qt*16);
    float4*       rptr = (float4*)(g_res + (size_t)(row0+row)*DD + qt*16);
    float4*       qptr = (float4*)(g_q   + (size_t)(row0+row)*DD + qt*16);
    __half* th = g_resh16 + (size_t)(row0+row)*DD + qt*16;
    __half* tl = g_resl16 + (size_t)(row0+row)*DD + qt*16;
    float lsum = 0.0f;
    #pragma unroll
    for (int u = 0; u < 4; u++) {
        float4 q4 = qv[u];
        float4 r4 = rptr[u];
        float e0 = q4.x - r4.x, e1 = q4.y - r4.y, e2 = q4.z - r4.z, e3 = q4.w - r4.w;
        lsum += e0*e0 + e1*e1 + e2*e2 + e3*e3;
        float4 rn; rn.x = -e0; rn.y = -e1; rn.z = -e2; rn.w = -e3;
        rptr[u] = rn;
        float4 qa = qptr[u];
        qa.x += q4.x; qa.y += q4.y; qa.z += q4.z; qa.w += q4.w;
        qptr[u] = qa;
        float nv[4] = {rn.x, rn.y, rn.z, rn.w};
        #pragma unroll
        for (int e = 0; e < 4; e++) {
            __half h = __float2half_rn(nv[e]);
            __half l = __float2half_rn(nv[e] - __half2float(h));
            th[u*4 + e] = h;
            tl[u*4 + e] = l;
        }
    }

    __syncthreads();
    #pragma unroll
    for (int o = 16; o > 0; o >>= 1) lsum += __shfl_down_sync(0xffffffffu, lsum, o);
    if ((tid & 31) == 0) red[tid >> 5] = lsum;
    __syncthreads();
    if (tid == 0) {
        float tot = 0.0f;
        #pragma unroll
        for (int ww = 0; ww < 16; ww++) tot += red[ww];
        atomicAdd(&g_loss[stage], tot);
    }
}

// ---- losses + perplexities ----
__global__ void finalize(float* __restrict__ out) {
    const int s = blockIdx.x;
    __shared__ float sh[256];
    float e = 0.0f;
    for (int k = threadIdx.x; k < KK; k += 256) {
        float p = (float)g_cnt[s*KK + k] / (float)NV;
        e += p * logf(p + 1e-10f);
    }
    sh[threadIdx.x] = e;
    __syncthreads();
    for (int o = 128; o > 0; o >>= 1) {
        if (threadIdx.x < o) sh[threadIdx.x] += sh[threadIdx.x + o];
        __syncthreads();
    }
    if (threadIdx.x == 0) {
        out[ZQ_ELEMS + s]      = g_loss[s] / (float)(NV*DD);
        out[ZQ_ELEMS + SS + s] = expf(-sh[0]);
    }
}

extern "C" void kernel_launch(void* const* d_in, const int* in_sizes, int n_in,
                              void* d_out, int out_size) {
    const float* z   = (const float*)d_in[0];
    const float* cbs = (const float*)d_in[1];
    float* out = (float*)d_out;

    static int inited = 0;
    if (!inited) {
        cudaFuncSetAttribute(rvq_stage, cudaFuncAttributeMaxDynamicSharedMemorySize, SM_TOTAL);
        inited = 1;
    }

    dim3 tb(32, 8);
    transpose_in<<<dim3(TT/32, DD/32, NB), tb>>>(z);
    zero_acc<<<32, 256>>>();
    cb_split<<<(SS*KK)/128, 128>>>(cbs);
    for (int s = 0; s < SS; s++) {
        rvq_stage<<<NV/TM, 512, SM_TOTAL>>>(cbs + (size_t)s*KK*DD, s);
    }
    finalize<<<SS, 256>>>(out);
    transpose_out<<<dim3(TT/32, DD/32, NB), tb>>>(out);
}

// round 7
// speedup vs baseline: 1.6672x; 1.0376x over previous
#include <cuda_runtime.h>
#include <cuda_fp16.h>
#include <float.h>
#include <cstdint>

#define NB   16
#define TT   4096
#define DD   64
#define KK   1024
#define SS   8
#define NV   (NB*TT)
#define TM   128
#define ZQ_ELEMS (NB*DD*TT)

// ---- device scratch ----
__device__ float        g_res[NV*DD];
__device__ float        g_q[NV*DD];
__device__ __half       g_resh16[NV*DD];
__device__ __half       g_resl16[NV*DD];
// fragment-packed codebook: [stage][blk(128)][kstep(4)][hl(2)][lane(32)][4 halves]
__device__ __half       g_cbfrag[SS*128*4*2*32*4];
__device__ float        g_hn[SS*KK];
__device__ float        g_loss[SS];
__device__ unsigned int g_cnt[SS*KK];

// ---- smem layout (bytes) ----
#define RSTR     144            // padded A row stride bytes (72 fp16)
#define TILE_B   (128*RSTR)     // 18432
#define SM_HN    0
#define SM_FIN   4096
#define SM_REDV  4608
#define SM_REDI  5632
#define SM_RED   6656
#define SM_AH    8192
#define SM_AL    (SM_AH + TILE_B)
#define SM_TOTAL (SM_AL + TILE_B)   // 45056

// ---- PTX helpers ----
__device__ __forceinline__ void cpa16(uint32_t daddr, const void* src) {
    asm volatile("cp.async.cg.shared.global [%0], [%1], 16;" :: "r"(daddr), "l"(src) : "memory");
}
__device__ __forceinline__ void cpa_commit() { asm volatile("cp.async.commit_group;" ::: "memory"); }
__device__ __forceinline__ void cpa_wait0()  { asm volatile("cp.async.wait_group 0;" ::: "memory"); }

__device__ __forceinline__ void ldsm_x4(uint32_t* r, uint32_t a) {
    asm volatile("ldmatrix.sync.aligned.m8n8.x4.shared.b16 {%0,%1,%2,%3}, [%4];"
        : "=r"(r[0]), "=r"(r[1]), "=r"(r[2]), "=r"(r[3]) : "r"(a));
}
__device__ __forceinline__ void mma16816(float* c, const uint32_t* a, const uint32_t* b) {
    asm volatile("mma.sync.aligned.m16n8k16.row.col.f32.f16.f16.f32 "
        "{%0,%1,%2,%3}, {%4,%5,%6,%7}, {%8,%9}, {%0,%1,%2,%3};"
        : "+f"(c[0]), "+f"(c[1]), "+f"(c[2]), "+f"(c[3])
        : "r"(a[0]), "r"(a[1]), "r"(a[2]), "r"(a[3]), "r"(b[0]), "r"(b[1]));
}

// ---- transpose z [B,D,T] -> g_res [(b,t),d] + fp16 hi/lo; zero g_q ----
__global__ void transpose_in(const float* __restrict__ z) {
    __shared__ float tile[32][33];
    const int b  = blockIdx.z;
    const int t0 = blockIdx.x * 32;
    const int d0 = blockIdx.y * 32;
    #pragma unroll
    for (int j = 0; j < 32; j += 8)
        tile[threadIdx.y + j][threadIdx.x] = z[(b*DD + d0 + threadIdx.y + j)*TT + t0 + threadIdx.x];
    __syncthreads();
    #pragma unroll
    for (int j = 0; j < 32; j += 8) {
        int t = t0 + threadIdx.y + j;
        int d = d0 + threadIdx.x;
        int n = b*TT + t;
        float v = tile[threadIdx.x][threadIdx.y + j];
        g_res[n*DD + d] = v;
        g_q[n*DD + d]   = 0.0f;
        __half h = __float2half_rn(v);
        __half l = __float2half_rn(v - __half2float(h));
        g_resh16[n*DD + d] = h;
        g_resl16[n*DD + d] = l;
    }
}

__global__ void transpose_out(float* __restrict__ out) {
    __shared__ float tile[32][33];
    const int b  = blockIdx.z;
    const int t0 = blockIdx.x * 32;
    const int d0 = blockIdx.y * 32;
    #pragma unroll
    for (int j = 0; j < 32; j += 8)
        tile[threadIdx.y + j][threadIdx.x] = g_q[((size_t)b*TT + t0 + threadIdx.y + j)*DD + d0 + threadIdx.x];
    __syncthreads();
    #pragma unroll
    for (int j = 0; j < 32; j += 8)
        out[((size_t)b*DD + d0 + threadIdx.y + j)*TT + t0 + threadIdx.x] = tile[threadIdx.x][threadIdx.y + j];
}

// ---- codebook -> fragment-packed layout + halfnorms ----
// fragment for mma m16n8k16 B: lane l holds codes n = blk*8 + l/4,
// k halves: b0 = kstep*16 + (l%4)*2 + {0,1}, b1 = +8. 4 halves per lane.
__global__ void cb_split(const float* __restrict__ cbs) {
    int g = blockIdx.x * 128 + threadIdx.x;   // 0..8191 = s*1024 + j
    int s    = g >> 10;
    int j    = g & 1023;
    int blk  = j >> 3;
    int n_ib = j & 7;
    const float* src = cbs + (size_t)g * DD;
    __half* base = g_cbfrag + ((size_t)s*128*8 ) * 128;   // per stage: 128 blk * 8 frag * 128 halves
    float s2 = 0.0f;
    #pragma unroll
    for (int k = 0; k < DD; k++) {
        float v = src[k];
        s2 += v*v;
        __half h = __float2half_rn(v);
        __half l = __float2half_rn(v - __half2float(h));
        int kstep = k >> 4, kk = k & 15;
        int reg  = kk >> 3;
        int lane = n_ib*4 + ((kk & 7) >> 1);
        int elem = kk & 1;
        size_t fh = ((size_t)(blk*8 + kstep*2 + 0)*32 + lane)*4 + reg*2 + elem;
        size_t fl = ((size_t)(blk*8 + kstep*2 + 1)*32 + lane)*4 + reg*2 + elem;
        base[fh] = h;
        base[fl] = l;
    }
    g_hn[g] = 0.5f * s2;
}

__global__ void zero_acc() {
    int i = blockIdx.x * 256 + threadIdx.x;
    if (i < SS*KK) g_cnt[i] = 0u;
    if (i < SS)    g_loss[i] = 0.0f;
}

// ---- main stage kernel: 512 threads, 16 warps = 8 row-groups x 2 code-halves,
//      no mainloop barriers; B fragments streamed via __ldg from g_cbfrag ----
extern __shared__ char smem_raw[];

__global__ __launch_bounds__(512, 1)
void rvq_stage(const float* __restrict__ cb, int stage) {
    const int tid  = threadIdx.x;
    const int w    = tid >> 5;
    const int lane = tid & 31;
    const int wrow = w >> 1;          // 0..7: rows wrow*16..+15
    const int wcol = w & 1;           // 0..1: blocks wcol*64..+63
    const int row0 = blockIdx.x * TM;
    uint32_t sb;
    asm("{ .reg .u64 t; cvta.to.shared.u64 t, %1; cvt.u32.u64 %0, t; }" : "=r"(sb) : "l"(smem_raw));

    float* hn_s = (float*)(smem_raw + SM_HN);
    int*   fin  = (int*)(smem_raw + SM_FIN);
    float* redV = (float*)(smem_raw + SM_REDV);   // [128][2]
    int*   redI = (int*)(smem_raw + SM_REDI);     // [128][2]
    float* red  = (float*)(smem_raw + SM_RED);

    // ---- prologue: cp.async A(h,l) + hn, one barrier ----
    {
        const char* ah = (const char*)(g_resh16 + (size_t)row0*DD);
        const char* al = (const char*)(g_resl16 + (size_t)row0*DD);
        #pragma unroll
        for (int g = 0; g < 2; g++) {
            int idx = g*512 + tid;              // 1024 granules per tile
            int r = idx >> 3, cc = idx & 7;
            uint32_t dof = r*RSTR + cc*16;
            int sof = r*128 + cc*16;
            cpa16(sb + SM_AH + dof, ah + sof);
            cpa16(sb + SM_AL + dof, al + sof);
        }
        if (tid < 256) cpa16(sb + SM_HN + tid*16, (const char*)(g_hn + stage*KK) + tid*16);
        cpa_commit();
        cpa_wait0();
    }
    __syncthreads();

    uint32_t ahf[4][4], alf[4][4];
    const uint32_t a_addr = sb + SM_AH + (wrow*16 + (lane & 15))*RSTR + (lane >> 4)*16;
    #pragma unroll
    for (int s = 0; s < 4; s++) {
        ldsm_x4(ahf[s], a_addr + s*32);
        ldsm_x4(alf[s], a_addr + TILE_B + s*32);
    }

    // per-lane base into fragment-packed codebook (uint2 granularity)
    const uint2* bf = ((const uint2*)g_cbfrag) + (size_t)stage*32768 + lane;

    float bv0 = -FLT_MAX, bv1 = -FLT_MAX;
    int   bi0 = 0,        bi1 = 0;

    for (int cg = 0; cg < 8; cg++) {
        const int blk0  = wcol*64 + cg*8;
        const int cbase = blk0*8 + (lane & 3)*2;

        // init accumulators with -0.5||c||^2 (HMMA accumulates on top)
        float acc[8][4];
        #pragma unroll
        for (int nb = 0; nb < 8; nb++) {
            float h0 = -hn_s[cbase + nb*8];
            float h1 = -hn_s[cbase + nb*8 + 1];
            acc[nb][0] = h0; acc[nb][1] = h1; acc[nb][2] = h0; acc[nb][3] = h1;
        }

        #pragma unroll
        for (int s = 0; s < 4; s++) {
            #pragma unroll
            for (int nb = 0; nb < 8; nb++) {
                const uint2* p = bf + ((size_t)(blk0 + nb)*8 + s*2)*32;
                uint2 bh = __ldg(p);
                uint2 bl = __ldg(p + 32);
                mma16816(acc[nb], ahf[s], (const uint32_t*)&bh);
                mma16816(acc[nb], ahf[s], (const uint32_t*)&bl);
                mma16816(acc[nb], alf[s], (const uint32_t*)&bh);
            }
        }

        // argmax fold: thread owns rows wrow*16 + lane/4 and +8
        #pragma unroll
        for (int nb = 0; nb < 8; nb++) {
            int col = cbase + nb*8;
            if (acc[nb][0] > bv0) { bv0 = acc[nb][0]; bi0 = col; }
            if (acc[nb][1] > bv0) { bv0 = acc[nb][1]; bi0 = col + 1; }
            if (acc[nb][2] > bv1) { bv1 = acc[nb][2]; bi1 = col; }
            if (acc[nb][3] > bv1) { bv1 = acc[nb][3]; bi1 = col + 1; }
        }
    }

    // ---- reduce over 4 lanes sharing a row ----
    #pragma unroll
    for (int off = 1; off <= 2; off <<= 1) {
        float ov = __shfl_xor_sync(0xffffffffu, bv0, off);
        int   oi = __shfl_xor_sync(0xffffffffu, bi0, off);
        if (ov > bv0 || (ov == bv0 && oi < bi0)) { bv0 = ov; bi0 = oi; }
        ov = __shfl_xor_sync(0xffffffffu, bv1, off);
        oi = __shfl_xor_sync(0xffffffffu, bi1, off);
        if (ov > bv1 || (ov == bv1 && oi < bi1)) { bv1 = ov; bi1 = oi; }
    }
    if ((lane & 3) == 0) {
        int r0 = wrow*16 + (lane >> 2);
        redV[r0*2 + wcol]       = bv0;  redI[r0*2 + wcol]       = bi0;
        redV[(r0 + 8)*2 + wcol] = bv1;  redI[(r0 + 8)*2 + wcol] = bi1;
    }
    __syncthreads();
    if (tid < TM) {
        float v0 = redV[tid*2], v1 = redV[tid*2 + 1];
        int   i0 = redI[tid*2], i1 = redI[tid*2 + 1];
        int   bi = (v1 > v0 || (v1 == v0 && i1 < i0)) ? i1 : i0;
        fin[tid] = bi;
        atomicAdd(&g_cnt[stage*KK + bi], 1u);
    }
    __syncthreads();

    // ---- update: 4 threads per row, 16 d's each ----
    const int row = tid >> 2;
    const int qt  = tid & 3;
    const int code = fin[row];
    const float4* qv   = (const float4*)(cb + (size_t)code*DD + qt*16);
    float4*       rptr = (float4*)(g_res + (size_t)(row0+row)*DD + qt*16);
    float4*       qptr = (float4*)(g_q   + (size_t)(row0+row)*DD + qt*16);
    __half* th = g_resh16 + (size_t)(row0+row)*DD + qt*16;
    __half* tl = g_resl16 + (size_t)(row0+row)*DD + qt*16;
    float lsum = 0.0f;
    #pragma unroll
    for (int u = 0; u < 4; u++) {
        float4 q4 = qv[u];
        float4 r4 = rptr[u];
        float e0 = q4.x - r4.x, e1 = q4.y - r4.y, e2 = q4.z - r4.z, e3 = q4.w - r4.w;
        lsum += e0*e0 + e1*e1 + e2*e2 + e3*e3;
        float4 rn; rn.x = -e0; rn.y = -e1; rn.z = -e2; rn.w = -e3;
        rptr[u] = rn;
        float4 qa = qptr[u];
        qa.x += q4.x; qa.y += q4.y; qa.z += q4.z; qa.w += q4.w;
        qptr[u] = qa;
        float nv[4] = {rn.x, rn.y, rn.z, rn.w};
        #pragma unroll
        for (int e = 0; e < 4; e++) {
            __half h = __float2half_rn(nv[e]);
            __half l = __float2half_rn(nv[e] - __half2float(h));
            th[u*4 + e] = h;
            tl[u*4 + e] = l;
        }
    }

    __syncthreads();
    #pragma unroll
    for (int o = 16; o > 0; o >>= 1) lsum += __shfl_down_sync(0xffffffffu, lsum, o);
    if ((tid & 31) == 0) red[tid >> 5] = lsum;
    __syncthreads();
    if (tid == 0) {
        float tot = 0.0f;
        #pragma unroll
        for (int ww = 0; ww < 16; ww++) tot += red[ww];
        atomicAdd(&g_loss[stage], tot);
    }
}

// ---- losses + perplexities ----
__global__ void finalize(float* __restrict__ out) {
    const int s = blockIdx.x;
    __shared__ float sh[256];
    float e = 0.0f;
    for (int k = threadIdx.x; k < KK; k += 256) {
        float p = (float)g_cnt[s*KK + k] / (float)NV;
        e += p * logf(p + 1e-10f);
    }
    sh[threadIdx.x] = e;
    __syncthreads();
    for (int o = 128; o > 0; o >>= 1) {
        if (threadIdx.x < o) sh[threadIdx.x] += sh[threadIdx.x + o];
        __syncthreads();
    }
    if (threadIdx.x == 0) {
        out[ZQ_ELEMS + s]      = g_loss[s] / (float)(NV*DD);
        out[ZQ_ELEMS + SS + s] = expf(-sh[0]);
    }
}

extern "C" void kernel_launch(void* const* d_in, const int* in_sizes, int n_in,
                              void* d_out, int out_size) {
    const float* z   = (const float*)d_in[0];
    const float* cbs = (const float*)d_in[1];
    float* out = (float*)d_out;

    static int inited = 0;
    if (!inited) {
        cudaFuncSetAttribute(rvq_stage, cudaFuncAttributeMaxDynamicSharedMemorySize, SM_TOTAL);
        inited = 1;
    }

    dim3 tb(32, 8);
    transpose_in<<<dim3(TT/32, DD/32, NB), tb>>>(z);
    zero_acc<<<32, 256>>>();
    cb_split<<<(SS*KK)/128, 128>>>(cbs);
    for (int s = 0; s < SS; s++) {
        rvq_stage<<<NV/TM, 512, SM_TOTAL>>>(cbs + (size_t)s*KK*DD, s);
    }
    finalize<<<SS, 256>>>(out);
    transpose_out<<<dim3(TT/32, DD/32, NB), tb>>>(out);
}

// round 8
// speedup vs baseline: 1.7274x; 1.0362x over previous
#include <cuda_runtime.h>
#include <cuda_fp16.h>
#include <float.h>
#include <cstdint>

#define NB   16
#define TT   4096
#define DD   64
#define KK   1024
#define SS   8
#define NV   (NB*TT)
#define TM   128
#define ZQ_ELEMS (NB*DD*TT)

// ---- device scratch ----
__device__ float        g_res[NV*DD];
__device__ float        g_q[NV*DD];
__device__ __half       g_resh16[NV*DD];
__device__ __half       g_resl16[NV*DD];
// fragment-packed codebook: [stage][blk(128)][kstep(4)][hl(2)][lane(32)][4 halves]
__device__ __half       g_cbfrag[SS*128*4*2*32*4];
__device__ float        g_hn[SS*KK];
__device__ float        g_loss[SS];
__device__ unsigned int g_cnt[SS*KK];

// ---- smem layout (bytes) ----
#define RSTR     144            // padded A row stride bytes (72 fp16)
#define TILE_B   (128*RSTR)     // 18432
#define SM_HN    0
#define SM_FIN   4096
#define SM_REDV  4608
#define SM_REDI  5632
#define SM_RED   6656
#define SM_AH    8192
#define SM_AL    (SM_AH + TILE_B)
#define SM_TOTAL (SM_AL + TILE_B)   // 45056

// ---- PTX helpers ----
__device__ __forceinline__ void cpa16(uint32_t daddr, const void* src) {
    asm volatile("cp.async.cg.shared.global [%0], [%1], 16;" :: "r"(daddr), "l"(src) : "memory");
}
__device__ __forceinline__ void cpa_commit() { asm volatile("cp.async.commit_group;" ::: "memory"); }
__device__ __forceinline__ void cpa_wait0()  { asm volatile("cp.async.wait_group 0;" ::: "memory"); }

__device__ __forceinline__ void ldsm_x4(uint32_t* r, uint32_t a) {
    asm volatile("ldmatrix.sync.aligned.m8n8.x4.shared.b16 {%0,%1,%2,%3}, [%4];"
        : "=r"(r[0]), "=r"(r[1]), "=r"(r[2]), "=r"(r[3]) : "r"(a));
}
__device__ __forceinline__ void mma16816(float* c, const uint32_t* a, const uint2& b) {
    asm volatile("mma.sync.aligned.m16n8k16.row.col.f32.f16.f16.f32 "
        "{%0,%1,%2,%3}, {%4,%5,%6,%7}, {%8,%9}, {%0,%1,%2,%3};"
        : "+f"(c[0]), "+f"(c[1]), "+f"(c[2]), "+f"(c[3])
        : "r"(a[0]), "r"(a[1]), "r"(a[2]), "r"(a[3]), "r"(b.x), "r"(b.y));
}

// ---- transpose z [B,D,T] -> g_res [(b,t),d] + fp16 hi/lo; zero g_q ----
__global__ void transpose_in(const float* __restrict__ z) {
    __shared__ float tile[32][33];
    const int b  = blockIdx.z;
    const int t0 = blockIdx.x * 32;
    const int d0 = blockIdx.y * 32;
    #pragma unroll
    for (int j = 0; j < 32; j += 8)
        tile[threadIdx.y + j][threadIdx.x] = z[(b*DD + d0 + threadIdx.y + j)*TT + t0 + threadIdx.x];
    __syncthreads();
    #pragma unroll
    for (int j = 0; j < 32; j += 8) {
        int t = t0 + threadIdx.y + j;
        int d = d0 + threadIdx.x;
        int n = b*TT + t;
        float v = tile[threadIdx.x][threadIdx.y + j];
        g_res[n*DD + d] = v;
        g_q[n*DD + d]   = 0.0f;
        __half h = __float2half_rn(v);
        __half l = __float2half_rn(v - __half2float(h));
        g_resh16[n*DD + d] = h;
        g_resl16[n*DD + d] = l;
    }
}

__global__ void transpose_out(float* __restrict__ out) {
    __shared__ float tile[32][33];
    const int b  = blockIdx.z;
    const int t0 = blockIdx.x * 32;
    const int d0 = blockIdx.y * 32;
    #pragma unroll
    for (int j = 0; j < 32; j += 8)
        tile[threadIdx.y + j][threadIdx.x] = g_q[((size_t)b*TT + t0 + threadIdx.y + j)*DD + d0 + threadIdx.x];
    __syncthreads();
    #pragma unroll
    for (int j = 0; j < 32; j += 8)
        out[((size_t)b*DD + d0 + threadIdx.y + j)*TT + t0 + threadIdx.x] = tile[threadIdx.x][threadIdx.y + j];
}

// ---- codebook -> fragment-packed layout + halfnorms ----
__global__ void cb_split(const float* __restrict__ cbs) {
    int g = blockIdx.x * 128 + threadIdx.x;   // 0..8191 = s*1024 + j
    int s    = g >> 10;
    int j    = g & 1023;
    int blk  = j >> 3;
    int n_ib = j & 7;
    const float* src = cbs + (size_t)g * DD;
    __half* base = g_cbfrag + ((size_t)s*128*8) * 128;
    float s2 = 0.0f;
    #pragma unroll
    for (int k = 0; k < DD; k++) {
        float v = src[k];
        s2 += v*v;
        __half h = __float2half_rn(v);
        __half l = __float2half_rn(v - __half2float(h));
        int kstep = k >> 4, kk = k & 15;
        int reg  = kk >> 3;
        int lane = n_ib*4 + ((kk & 7) >> 1);
        int elem = kk & 1;
        size_t fh = ((size_t)(blk*8 + kstep*2 + 0)*32 + lane)*4 + reg*2 + elem;
        size_t fl = ((size_t)(blk*8 + kstep*2 + 1)*32 + lane)*4 + reg*2 + elem;
        base[fh] = h;
        base[fl] = l;
    }
    g_hn[g] = 0.5f * s2;
}

__global__ void zero_acc() {
    int i = blockIdx.x * 256 + threadIdx.x;
    if (i < SS*KK) g_cnt[i] = 0u;
    if (i < SS)    g_loss[i] = 0.0f;
}

// ---- main stage kernel: 512 threads, 16 warps; software-pipelined 3-pass MMA ----
extern __shared__ char smem_raw[];

__global__ __launch_bounds__(512, 1)
void rvq_stage(const float* __restrict__ cb, int stage) {
    const int tid  = threadIdx.x;
    const int w    = tid >> 5;
    const int lane = tid & 31;
    const int wrow = w >> 1;          // 0..7: rows wrow*16..+15
    const int wcol = w & 1;           // 0..1: blocks wcol*64..+63
    const int row0 = blockIdx.x * TM;
    uint32_t sb;
    asm("{ .reg .u64 t; cvta.to.shared.u64 t, %1; cvt.u32.u64 %0, t; }" : "=r"(sb) : "l"(smem_raw));

    float* hn_s = (float*)(smem_raw + SM_HN);
    int*   fin  = (int*)(smem_raw + SM_FIN);
    float* redV = (float*)(smem_raw + SM_REDV);   // [128][2]
    int*   redI = (int*)(smem_raw + SM_REDI);     // [128][2]
    float* red  = (float*)(smem_raw + SM_RED);

    // ---- prologue: cp.async A(h,l) + hn, one barrier ----
    {
        const char* ah = (const char*)(g_resh16 + (size_t)row0*DD);
        const char* al = (const char*)(g_resl16 + (size_t)row0*DD);
        #pragma unroll
        for (int g = 0; g < 2; g++) {
            int idx = g*512 + tid;
            int r = idx >> 3, cc = idx & 7;
            uint32_t dof = r*RSTR + cc*16;
            int sof = r*128 + cc*16;
            cpa16(sb + SM_AH + dof, ah + sof);
            cpa16(sb + SM_AL + dof, al + sof);
        }
        if (tid < 256) cpa16(sb + SM_HN + tid*16, (const char*)(g_hn + stage*KK) + tid*16);
        cpa_commit();
        cpa_wait0();
    }
    __syncthreads();

    uint32_t ahf[4][4], alf[4][4];
    const uint32_t a_addr = sb + SM_AH + (wrow*16 + (lane & 15))*RSTR + (lane >> 4)*16;
    #pragma unroll
    for (int s = 0; s < 4; s++) {
        ldsm_x4(ahf[s], a_addr + s*32);
        ldsm_x4(alf[s], a_addr + TILE_B + s*32);
    }

    // per-lane base into fragment-packed codebook (uint2 granularity)
    const uint2* bf = ((const uint2*)g_cbfrag) + (size_t)stage*32768 + lane;

    float bv0 = -FLT_MAX, bv1 = -FLT_MAX;
    int   bi0 = 0,        bi1 = 0;

    for (int cg = 0; cg < 8; cg++) {
        const int blk0  = wcol*64 + cg*8;
        const int cbase = blk0*8 + (lane & 3)*2;

        // init accumulators with -0.5||c||^2 (HMMA accumulates on top)
        float acc[8][4];
        #pragma unroll
        for (int nb = 0; nb < 8; nb++) {
            float h0 = -hn_s[cbase + nb*8];
            float h1 = -hn_s[cbase + nb*8 + 1];
            acc[nb][0] = h0; acc[nb][1] = h1; acc[nb][2] = h0; acc[nb][3] = h1;
        }

        #pragma unroll
        for (int s = 0; s < 4; s++) {
            // batch-load all B fragments for this k-step (16 independent LDGs)
            uint2 bh[8], bl[8];
            #pragma unroll
            for (int nb = 0; nb < 8; nb++) {
                const uint2* p = bf + ((size_t)(blk0 + nb)*8 + s*2)*32;
                bh[nb] = __ldg(p);
                bl[nb] = __ldg(p + 32);
            }
            // pass 1: ah*bh — 8 independent MMAs
            #pragma unroll
            for (int nb = 0; nb < 8; nb++) mma16816(acc[nb], ahf[s], bh[nb]);
            // pass 2: al*bh
            #pragma unroll
            for (int nb = 0; nb < 8; nb++) mma16816(acc[nb], alf[s], bh[nb]);
            // pass 3: ah*bl
            #pragma unroll
            for (int nb = 0; nb < 8; nb++) mma16816(acc[nb], ahf[s], bl[nb]);
        }

        // argmax fold: thread owns rows wrow*16 + lane/4 and +8
        #pragma unroll
        for (int nb = 0; nb < 8; nb++) {
            int col = cbase + nb*8;
            if (acc[nb][0] > bv0) { bv0 = acc[nb][0]; bi0 = col; }
            if (acc[nb][1] > bv0) { bv0 = acc[nb][1]; bi0 = col + 1; }
            if (acc[nb][2] > bv1) { bv1 = acc[nb][2]; bi1 = col; }
            if (acc[nb][3] > bv1) { bv1 = acc[nb][3]; bi1 = col + 1; }
        }
    }

    // ---- reduce over 4 lanes sharing a row ----
    #pragma unroll
    for (int off = 1; off <= 2; off <<= 1) {
        float ov = __shfl_xor_sync(0xffffffffu, bv0, off);
        int   oi = __shfl_xor_sync(0xffffffffu, bi0, off);
        if (ov > bv0 || (ov == bv0 && oi < bi0)) { bv0 = ov; bi0 = oi; }
        ov = __shfl_xor_sync(0xffffffffu, bv1, off);
        oi = __shfl_xor_sync(0xffffffffu, bi1, off);
        if (ov > bv1 || (ov == bv1 && oi < bi1)) { bv1 = ov; bi1 = oi; }
    }
    if ((lane & 3) == 0) {
        int r0 = wrow*16 + (lane >> 2);
        redV[r0*2 + wcol]       = bv0;  redI[r0*2 + wcol]       = bi0;
        redV[(r0 + 8)*2 + wcol] = bv1;  redI[(r0 + 8)*2 + wcol] = bi1;
    }
    __syncthreads();
    if (tid < TM) {
        float v0 = redV[tid*2], v1 = redV[tid*2 + 1];
        int   i0 = redI[tid*2], i1 = redI[tid*2 + 1];
        int   bi = (v1 > v0 || (v1 == v0 && i1 < i0)) ? i1 : i0;
        fin[tid] = bi;
        atomicAdd(&g_cnt[stage*KK + bi], 1u);
    }
    __syncthreads();

    // ---- update: 4 threads per row, 16 d's each ----
    const int row = tid >> 2;
    const int qt  = tid & 3;
    const int code = fin[row];
    const float4* qv   = (const float4*)(cb + (size_t)code*DD + qt*16);
    float4*       rptr = (float4*)(g_res + (size_t)(row0+row)*DD + qt*16);
    float4*       qptr = (float4*)(g_q   + (size_t)(row0+row)*DD + qt*16);
    __half* th = g_resh16 + (size_t)(row0+row)*DD + qt*16;
    __half* tl = g_resl16 + (size_t)(row0+row)*DD + qt*16;
    float lsum = 0.0f;
    #pragma unroll
    for (int u = 0; u < 4; u++) {
        float4 q4 = qv[u];
        float4 r4 = rptr[u];
        float e0 = q4.x - r4.x, e1 = q4.y - r4.y, e2 = q4.z - r4.z, e3 = q4.w - r4.w;
        lsum += e0*e0 + e1*e1 + e2*e2 + e3*e3;
        float4 rn; rn.x = -e0; rn.y = -e1; rn.z = -e2; rn.w = -e3;
        rptr[u] = rn;
        float4 qa = qptr[u];
        qa.x += q4.x; qa.y += q4.y; qa.z += q4.z; qa.w += q4.w;
        qptr[u] = qa;
        float nv[4] = {rn.x, rn.y, rn.z, rn.w};
        #pragma unroll
        for (int e = 0; e < 4; e++) {
            __half h = __float2half_rn(nv[e]);
            __half l = __float2half_rn(nv[e] - __half2float(h));
            th[u*4 + e] = h;
            tl[u*4 + e] = l;
        }
    }

    __syncthreads();
    #pragma unroll
    for (int o = 16; o > 0; o >>= 1) lsum += __shfl_down_sync(0xffffffffu, lsum, o);
    if ((tid & 31) == 0) red[tid >> 5] = lsum;
    __syncthreads();
    if (tid == 0) {
        float tot = 0.0f;
        #pragma unroll
        for (int ww = 0; ww < 16; ww++) tot += red[ww];
        atomicAdd(&g_loss[stage], tot);
    }
}

// ---- losses + perplexities ----
__global__ void finalize(float* __restrict__ out) {
    const int s = blockIdx.x;
    __shared__ float sh[256];
    float e = 0.0f;
    for (int k = threadIdx.x; k < KK; k += 256) {
        float p = (float)g_cnt[s*KK + k] / (float)NV;
        e += p * logf(p + 1e-10f);
    }
    sh[threadIdx.x] = e;
    __syncthreads();
    for (int o = 128; o > 0; o >>= 1) {
        if (threadIdx.x < o) sh[threadIdx.x] += sh[threadIdx.x + o];
        __syncthreads();
    }
    if (threadIdx.x == 0) {
        out[ZQ_ELEMS + s]      = g_loss[s] / (float)(NV*DD);
        out[ZQ_ELEMS + SS + s] = expf(-sh[0]);
    }
}

extern "C" void kernel_launch(void* const* d_in, const int* in_sizes, int n_in,
                              void* d_out, int out_size) {
    const float* z   = (const float*)d_in[0];
    const float* cbs = (const float*)d_in[1];
    float* out = (float*)d_out;

    static int inited = 0;
    if (!inited) {
        cudaFuncSetAttribute(rvq_stage, cudaFuncAttributeMaxDynamicSharedMemorySize, SM_TOTAL);
        inited = 1;
    }

    dim3 tb(32, 8);
    transpose_in<<<dim3(TT/32, DD/32, NB), tb>>>(z);
    zero_acc<<<32, 256>>>();
    cb_split<<<(SS*KK)/128, 128>>>(cbs);
    for (int s = 0; s < SS; s++) {
        rvq_stage<<<NV/TM, 512, SM_TOTAL>>>(cbs + (size_t)s*KK*DD, s);
    }
    finalize<<<SS, 256>>>(out);
    transpose_out<<<dim3(TT/32, DD/32, NB), tb>>>(out);
}

// round 9
// speedup vs baseline: 1.9751x; 1.1433x over previous
#include <cuda_runtime.h>
#include <cuda_fp16.h>
#include <float.h>
#include <cstdint>

#define NB   16
#define TT   4096
#define DD   64
#define KK   1024
#define SS   8
#define NV   (NB*TT)
#define TM   64
#define ZQ_ELEMS (NB*DD*TT)

// ---- device scratch ----
__device__ float        g_res[NV*DD];
__device__ float        g_q[NV*DD];
__device__ __half       g_resh16[NV*DD];
__device__ __half       g_resl16[NV*DD];
// fragment-packed codebook: [stage][blk(128)][kstep(4)][hl(2)][lane(32)][4 halves]
__device__ __half       g_cbfrag[SS*128*4*2*32*4];
__device__ float        g_hn[SS*KK];
__device__ float        g_loss[SS];
__device__ unsigned int g_cnt[SS*KK];

// ---- smem layout (bytes) ----
#define RSTR     144            // padded A row stride bytes (72 fp16)
#define TILE_A   (TM*RSTR)      // 9216
#define SM_HN    0
#define SM_FIN   4096
#define SM_REDV  4608
#define SM_REDI  5632
#define SM_RED   6656
#define SM_AH    8192
#define SM_AL    (SM_AH + TILE_A)
#define SM_TOTAL (SM_AL + TILE_A)   // 26624

// ---- PTX helpers ----
__device__ __forceinline__ void cpa16(uint32_t daddr, const void* src) {
    asm volatile("cp.async.cg.shared.global [%0], [%1], 16;" :: "r"(daddr), "l"(src) : "memory");
}
__device__ __forceinline__ void cpa_commit() { asm volatile("cp.async.commit_group;" ::: "memory"); }
__device__ __forceinline__ void cpa_wait0()  { asm volatile("cp.async.wait_group 0;" ::: "memory"); }

__device__ __forceinline__ void ldsm_x4(uint32_t* r, uint32_t a) {
    asm volatile("ldmatrix.sync.aligned.m8n8.x4.shared.b16 {%0,%1,%2,%3}, [%4];"
        : "=r"(r[0]), "=r"(r[1]), "=r"(r[2]), "=r"(r[3]) : "r"(a));
}
__device__ __forceinline__ void mma16816(float* c, const uint32_t* a, const uint2& b) {
    asm volatile("mma.sync.aligned.m16n8k16.row.col.f32.f16.f16.f32 "
        "{%0,%1,%2,%3}, {%4,%5,%6,%7}, {%8,%9}, {%0,%1,%2,%3};"
        : "+f"(c[0]), "+f"(c[1]), "+f"(c[2]), "+f"(c[3])
        : "r"(a[0]), "r"(a[1]), "r"(a[2]), "r"(a[3]), "r"(b.x), "r"(b.y));
}

// ---- transpose z [B,D,T] -> g_res [(b,t),d] + fp16 hi/lo; zero g_q ----
__global__ void transpose_in(const float* __restrict__ z) {
    __shared__ float tile[32][33];
    const int b  = blockIdx.z;
    const int t0 = blockIdx.x * 32;
    const int d0 = blockIdx.y * 32;
    #pragma unroll
    for (int j = 0; j < 32; j += 8)
        tile[threadIdx.y + j][threadIdx.x] = z[(b*DD + d0 + threadIdx.y + j)*TT + t0 + threadIdx.x];
    __syncthreads();
    #pragma unroll
    for (int j = 0; j < 32; j += 8) {
        int t = t0 + threadIdx.y + j;
        int d = d0 + threadIdx.x;
        int n = b*TT + t;
        float v = tile[threadIdx.x][threadIdx.y + j];
        g_res[n*DD + d] = v;
        g_q[n*DD + d]   = 0.0f;
        __half h = __float2half_rn(v);
        __half l = __float2half_rn(v - __half2float(h));
        g_resh16[n*DD + d] = h;
        g_resl16[n*DD + d] = l;
    }
}

__global__ void transpose_out(float* __restrict__ out) {
    __shared__ float tile[32][33];
    const int b  = blockIdx.z;
    const int t0 = blockIdx.x * 32;
    const int d0 = blockIdx.y * 32;
    #pragma unroll
    for (int j = 0; j < 32; j += 8)
        tile[threadIdx.y + j][threadIdx.x] = g_q[((size_t)b*TT + t0 + threadIdx.y + j)*DD + d0 + threadIdx.x];
    __syncthreads();
    #pragma unroll
    for (int j = 0; j < 32; j += 8)
        out[((size_t)b*DD + d0 + threadIdx.y + j)*TT + t0 + threadIdx.x] = tile[threadIdx.x][threadIdx.y + j];
}

// ---- codebook -> fragment-packed layout + halfnorms ----
__global__ void cb_split(const float* __restrict__ cbs) {
    int g = blockIdx.x * 128 + threadIdx.x;   // 0..8191 = s*1024 + j
    int s    = g >> 10;
    int j    = g & 1023;
    int blk  = j >> 3;
    int n_ib = j & 7;
    const float* src = cbs + (size_t)g * DD;
    __half* base = g_cbfrag + ((size_t)s*128*8) * 128;
    float s2 = 0.0f;
    #pragma unroll
    for (int k = 0; k < DD; k++) {
        float v = src[k];
        s2 += v*v;
        __half h = __float2half_rn(v);
        __half l = __float2half_rn(v - __half2float(h));
        int kstep = k >> 4, kk = k & 15;
        int reg  = kk >> 3;
        int lane = n_ib*4 + ((kk & 7) >> 1);
        int elem = kk & 1;
        size_t fh = ((size_t)(blk*8 + kstep*2 + 0)*32 + lane)*4 + reg*2 + elem;
        size_t fl = ((size_t)(blk*8 + kstep*2 + 1)*32 + lane)*4 + reg*2 + elem;
        base[fh] = h;
        base[fl] = l;
    }
    g_hn[g] = 0.5f * s2;
}

__global__ void zero_acc() {
    int i = blockIdx.x * 256 + threadIdx.x;
    if (i < SS*KK) g_cnt[i] = 0u;
    if (i < SS)    g_loss[i] = 0.0f;
}

// ---- main stage kernel: 256 threads (8 warps), 2 CTAs/SM, reg-pipelined B ----
extern __shared__ char smem_raw[];

__global__ __launch_bounds__(256, 2)
void rvq_stage(const float* __restrict__ cb, int stage) {
    const int tid  = threadIdx.x;
    const int w    = tid >> 5;
    const int lane = tid & 31;
    const int wrow = w >> 1;          // 0..3: rows wrow*16..+15
    const int wcol = w & 1;           // 0..1: blocks wcol*64..+63
    const int row0 = blockIdx.x * TM;
    uint32_t sb;
    asm("{ .reg .u64 t; cvta.to.shared.u64 t, %1; cvt.u32.u64 %0, t; }" : "=r"(sb) : "l"(smem_raw));

    float* hn_s = (float*)(smem_raw + SM_HN);
    int*   fin  = (int*)(smem_raw + SM_FIN);
    float* redV = (float*)(smem_raw + SM_REDV);   // [64][2]
    int*   redI = (int*)(smem_raw + SM_REDI);     // [64][2]
    float* red  = (float*)(smem_raw + SM_RED);

    // ---- prologue: cp.async A(h,l) + hn, one barrier ----
    {
        const char* ah = (const char*)(g_resh16 + (size_t)row0*DD);
        const char* al = (const char*)(g_resl16 + (size_t)row0*DD);
        #pragma unroll
        for (int g = 0; g < 2; g++) {
            int idx = g*256 + tid;              // 512 granules per tile
            int r = idx >> 3, cc = idx & 7;
            uint32_t dof = r*RSTR + cc*16;
            int sof = r*128 + cc*16;
            cpa16(sb + SM_AH + dof, ah + sof);
            cpa16(sb + SM_AL + dof, al + sof);
        }
        cpa16(sb + SM_HN + tid*16, (const char*)(g_hn + stage*KK) + tid*16);
        cpa_commit();
        cpa_wait0();
    }
    __syncthreads();

    uint32_t ahf[4][4], alf[4][4];
    const uint32_t a_addr = sb + SM_AH + (wrow*16 + (lane & 15))*RSTR + (lane >> 4)*16;
    #pragma unroll
    for (int s = 0; s < 4; s++) {
        ldsm_x4(ahf[s], a_addr + s*32);
        ldsm_x4(alf[s], a_addr + TILE_A + s*32);
    }

    // per-lane base into fragment-packed codebook (uint2 granularity)
    const uint2* bf = ((const uint2*)g_cbfrag) + (size_t)stage*32768 + lane;

    float bv0 = -FLT_MAX, bv1 = -FLT_MAX;
    int   bi0 = 0,        bi1 = 0;

    for (int cg = 0; cg < 8; cg++) {
        const int blk0  = wcol*64 + cg*8;
        const int cbase = blk0*8 + (lane & 3)*2;

        // init accumulators with -0.5||c||^2 (HMMA accumulates on top)
        float acc[8][4];
        #pragma unroll
        for (int nb = 0; nb < 8; nb++) {
            float h0 = -hn_s[cbase + nb*8];
            float h1 = -hn_s[cbase + nb*8 + 1];
            acc[nb][0] = h0; acc[nb][1] = h1; acc[nb][2] = h0; acc[nb][3] = h1;
        }

        // 2-stage register pipeline over (s, half): half = 4 blocks
        uint2 b0h[4], b0l[4], b1h[4], b1l[4];
        #pragma unroll
        for (int i = 0; i < 4; i++) {
            const uint2* p = bf + ((size_t)(blk0 + i)*8 + 0)*32;
            b0h[i] = __ldg(p);
            b0l[i] = __ldg(p + 32);
        }
        #pragma unroll
        for (int s = 0; s < 4; s++) {
            // prefetch half1 of this s
            #pragma unroll
            for (int i = 0; i < 4; i++) {
                const uint2* p = bf + ((size_t)(blk0 + 4 + i)*8 + s*2)*32;
                b1h[i] = __ldg(p);
                b1l[i] = __ldg(p + 32);
            }
            // compute half0 (12 MMAs)
            #pragma unroll
            for (int i = 0; i < 4; i++) mma16816(acc[i], ahf[s], b0h[i]);
            #pragma unroll
            for (int i = 0; i < 4; i++) mma16816(acc[i], alf[s], b0h[i]);
            #pragma unroll
            for (int i = 0; i < 4; i++) mma16816(acc[i], ahf[s], b0l[i]);
            // prefetch half0 of next s
            if (s < 3) {
                #pragma unroll
                for (int i = 0; i < 4; i++) {
                    const uint2* p = bf + ((size_t)(blk0 + i)*8 + (s+1)*2)*32;
                    b0h[i] = __ldg(p);
                    b0l[i] = __ldg(p + 32);
                }
            }
            // compute half1 (12 MMAs)
            #pragma unroll
            for (int i = 0; i < 4; i++) mma16816(acc[4+i], ahf[s], b1h[i]);
            #pragma unroll
            for (int i = 0; i < 4; i++) mma16816(acc[4+i], alf[s], b1h[i]);
            #pragma unroll
            for (int i = 0; i < 4; i++) mma16816(acc[4+i], ahf[s], b1l[i]);
        }

        // argmax fold: thread owns rows wrow*16 + lane/4 and +8
        #pragma unroll
        for (int nb = 0; nb < 8; nb++) {
            int col = cbase + nb*8;
            if (acc[nb][0] > bv0) { bv0 = acc[nb][0]; bi0 = col; }
            if (acc[nb][1] > bv0) { bv0 = acc[nb][1]; bi0 = col + 1; }
            if (acc[nb][2] > bv1) { bv1 = acc[nb][2]; bi1 = col; }
            if (acc[nb][3] > bv1) { bv1 = acc[nb][3]; bi1 = col + 1; }
        }
    }

    // ---- reduce over 4 lanes sharing a row ----
    #pragma unroll
    for (int off = 1; off <= 2; off <<= 1) {
        float ov = __shfl_xor_sync(0xffffffffu, bv0, off);
        int   oi = __shfl_xor_sync(0xffffffffu, bi0, off);
        if (ov > bv0 || (ov == bv0 && oi < bi0)) { bv0 = ov; bi0 = oi; }
        ov = __shfl_xor_sync(0xffffffffu, bv1, off);
        oi = __shfl_xor_sync(0xffffffffu, bi1, off);
        if (ov > bv1 || (ov == bv1 && oi < bi1)) { bv1 = ov; bi1 = oi; }
    }
    if ((lane & 3) == 0) {
        int r0 = wrow*16 + (lane >> 2);
        redV[r0*2 + wcol]       = bv0;  redI[r0*2 + wcol]       = bi0;
        redV[(r0 + 8)*2 + wcol] = bv1;  redI[(r0 + 8)*2 + wcol] = bi1;
    }
    __syncthreads();
    if (tid < TM) {
        float v0 = redV[tid*2], v1 = redV[tid*2 + 1];
        int   i0 = redI[tid*2], i1 = redI[tid*2 + 1];
        int   bi = (v1 > v0 || (v1 == v0 && i1 < i0)) ? i1 : i0;
        fin[tid] = bi;
        atomicAdd(&g_cnt[stage*KK + bi], 1u);
    }
    __syncthreads();

    // ---- update: 4 threads per row, 16 d's each ----
    const int row = tid >> 2;
    const int qt  = tid & 3;
    const int code = fin[row];
    const float4* qv   = (const float4*)(cb + (size_t)code*DD + qt*16);
    float4*       rptr = (float4*)(g_res + (size_t)(row0+row)*DD + qt*16);
    float4*       qptr = (float4*)(g_q   + (size_t)(row0+row)*DD + qt*16);
    __half* th = g_resh16 + (size_t)(row0+row)*DD + qt*16;
    __half* tl = g_resl16 + (size_t)(row0+row)*DD + qt*16;
    float lsum = 0.0f;
    #pragma unroll
    for (int u = 0; u < 4; u++) {
        float4 q4 = qv[u];
        float4 r4 = rptr[u];
        float e0 = q4.x - r4.x, e1 = q4.y - r4.y, e2 = q4.z - r4.z, e3 = q4.w - r4.w;
        lsum += e0*e0 + e1*e1 + e2*e2 + e3*e3;
        float4 rn; rn.x = -e0; rn.y = -e1; rn.z = -e2; rn.w = -e3;
        rptr[u] = rn;
        float4 qa = qptr[u];
        qa.x += q4.x; qa.y += q4.y; qa.z += q4.z; qa.w += q4.w;
        qptr[u] = qa;
        float nv[4] = {rn.x, rn.y, rn.z, rn.w};
        #pragma unroll
        for (int e = 0; e < 4; e++) {
            __half h = __float2half_rn(nv[e]);
            __half l = __float2half_rn(nv[e] - __half2float(h));
            th[u*4 + e] = h;
            tl[u*4 + e] = l;
        }
    }

    __syncthreads();
    #pragma unroll
    for (int o = 16; o > 0; o >>= 1) lsum += __shfl_down_sync(0xffffffffu, lsum, o);
    if ((tid & 31) == 0) red[tid >> 5] = lsum;
    __syncthreads();
    if (tid == 0) {
        float tot = 0.0f;
        #pragma unroll
        for (int ww = 0; ww < 8; ww++) tot += red[ww];
        atomicAdd(&g_loss[stage], tot);
    }
}

// ---- losses + perplexities ----
__global__ void finalize(float* __restrict__ out) {
    const int s = blockIdx.x;
    __shared__ float sh[256];
    float e = 0.0f;
    for (int k = threadIdx.x; k < KK; k += 256) {
        float p = (float)g_cnt[s*KK + k] / (float)NV;
        e += p * logf(p + 1e-10f);
    }
    sh[threadIdx.x] = e;
    __syncthreads();
    for (int o = 128; o > 0; o >>= 1) {
        if (threadIdx.x < o) sh[threadIdx.x] += sh[threadIdx.x + o];
        __syncthreads();
    }
    if (threadIdx.x == 0) {
        out[ZQ_ELEMS + s]      = g_loss[s] / (float)(NV*DD);
        out[ZQ_ELEMS + SS + s] = expf(-sh[0]);
    }
}

extern "C" void kernel_launch(void* const* d_in, const int* in_sizes, int n_in,
                              void* d_out, int out_size) {
    const float* z   = (const float*)d_in[0];
    const float* cbs = (const float*)d_in[1];
    float* out = (float*)d_out;

    static int inited = 0;
    if (!inited) {
        cudaFuncSetAttribute(rvq_stage, cudaFuncAttributeMaxDynamicSharedMemorySize, SM_TOTAL);
        inited = 1;
    }

    dim3 tb(32, 8);
    transpose_in<<<dim3(TT/32, DD/32, NB), tb>>>(z);
    zero_acc<<<32, 256>>>();
    cb_split<<<(SS*KK)/128, 128>>>(cbs);
    for (int s = 0; s < SS; s++) {
        rvq_stage<<<NV/TM, 256, SM_TOTAL>>>(cbs + (size_t)s*KK*DD, s);
    }
    finalize<<<SS, 256>>>(out);
    transpose_out<<<dim3(TT/32, DD/32, NB), tb>>>(out);
}